// round 1
// baseline (speedup 1.0000x reference)
#include <cuda_runtime.h>
#include <math.h>

// Problem constants
#define NN   4
#define II   64
#define CCH  256
#define GG   8
#define CG   32
#define KS   9
#define HH   48
#define HWQ  (48*48)   // 2304
#define HD   40
#define DD   (40*40)   // 1600

// ---------------- scratch (device globals; no allocation allowed) -----------
__device__ float g_xh[NN*2*CCH*HWQ];     // [N][512][48*48] interleaved x/h per group
__device__ float g_q [NN*CCH*HWQ];       // [N][C][2304]
__device__ float g_k [NN*CCH*DD];        // [N][C][1600]
__device__ float g_v [NN*CCH*DD];
__device__ float g_a [NN*CCH*HWQ];
__device__ float g_gp[4][NN*CCH*HWQ];    // gate pre-activations from Wxh convs (i,f,g,o)

__device__ __forceinline__ float sigm(float x) { return 1.f/(1.f+__expf(-x)); }

// ---------------- 1: projection + build xh ---------------------------------
// x = Wx*inp + Wxg*h ; xh channel layout per group g: [0..31]=x, [32..63]=h
__global__ __launch_bounds__(256)
void proj_kernel(const float* __restrict__ inp, const float* __restrict__ h,
                 const float* __restrict__ Wx, const float* __restrict__ Wxg)
{
    __shared__ float ws[8*320];
    int n  = blockIdx.z;
    int c0 = blockIdx.y * 8;
    int p0 = blockIdx.x * 256;
    int tid = threadIdx.x;

    for (int idx = tid; idx < 8*320; idx += 256) {
        int j = idx / 320, ic = idx - j*320;
        ws[idx] = (ic < 64) ? Wx[(c0+j)*64 + ic] : Wxg[(c0+j)*256 + (ic-64)];
    }
    __syncthreads();

    int p = p0 + tid;
    float acc[8];
#pragma unroll
    for (int j = 0; j < 8; ++j) acc[j] = 0.f;

    const float* ib = inp + (size_t)n*II*HWQ + p;
    const float* hb = h   + (size_t)n*CCH*HWQ + p;

#pragma unroll 4
    for (int ic = 0; ic < 64; ++ic) {
        float v = ib[ic*HWQ];
#pragma unroll
        for (int j = 0; j < 8; ++j) acc[j] = fmaf(ws[j*320+ic], v, acc[j]);
    }
#pragma unroll 4
    for (int ic = 0; ic < 256; ++ic) {
        float v = hb[ic*HWQ];
#pragma unroll
        for (int j = 0; j < 8; ++j) acc[j] = fmaf(ws[j*320+64+ic], v, acc[j]);
    }
#pragma unroll
    for (int j = 0; j < 8; ++j) {
        int c = c0 + j, g = c >> 5, cg = c & 31;
        g_xh[((n*2*CCH) + g*64      + cg)*HWQ + p] = acc[j];
        g_xh[((n*2*CCH) + g*64 + 32 + cg)*HWQ + p] = hb[c*HWQ];
    }
}

// ---------------- 2: grouped KxK conv (SAME: q + 4 gates, VALID: k,v) -------
// block: 16x16 spatial tile x 32 out-channels for one (conv, n, g).
// thread: 4 spatial rows x 8 channels = 32 fp32 accumulators.
template<bool SAME>
__global__ __launch_bounds__(256)
void gconv_kernel(const float* __restrict__ W0, const float* __restrict__ W1,
                  const float* __restrict__ W2, const float* __restrict__ W3,
                  const float* __restrict__ W4)
{
    constexpr int OH   = SAME ? 48 : 40;
    constexpr int ISTR = 28;                 // padded row stride (bank-safe)
    __shared__ float ins[2*24*ISTR];
    __shared__ float ws [32*162];            // [co][ci(2)][81]

    int z    = blockIdx.z;
    int conv = z >> 5;
    int ng   = z & 31;
    int n = ng >> 3, g = ng & 7;

    const float* W; float* out;
    if (SAME) {
        switch (conv) {
            case 0:  W = W0; out = g_q;     break;
            case 1:  W = W1; out = g_gp[0]; break;
            case 2:  W = W2; out = g_gp[1]; break;
            case 3:  W = W3; out = g_gp[2]; break;
            default: W = W4; out = g_gp[3]; break;
        }
    } else {
        if (conv == 0) { W = W0; out = g_k; }
        else           { W = W1; out = g_v; }
    }

    int x0 = blockIdx.x*16, y0 = blockIdx.y*16;
    int tid = threadIdx.x;
    int tx = tid & 15, ty4 = (tid >> 4) & 3, cq = tid >> 6;
    const int base = SAME ? -4 : 0;

    const float* xin = g_xh + ((size_t)(n*2*CCH) + g*64)*HWQ;
    const float* wg  = W + (size_t)(g*32)*64*81;

    float acc[4][8];
#pragma unroll
    for (int yy = 0; yy < 4; ++yy)
#pragma unroll
        for (int j = 0; j < 8; ++j) acc[yy][j] = 0.f;

    for (int ci0 = 0; ci0 < 64; ci0 += 2) {
        // stage input tile (2 ci x 24 x 24, zero-padded OOB)
        for (int idx = tid; idx < 2*576; idx += 256) {
            int ci = idx / 576; int rem = idx - ci*576;
            int r = rem / 24, cc = rem - r*24;
            int gy = y0 + base + r, gx = x0 + base + cc;
            float v = 0.f;
            if (gy >= 0 && gy < 48 && gx >= 0 && gx < 48)
                v = xin[(ci0+ci)*HWQ + gy*48 + gx];
            ins[ci*(24*ISTR) + r*ISTR + cc] = v;
        }
        // stage weights (32 co x 2 ci x 81)
        for (int idx = tid; idx < 32*162; idx += 256) {
            int co = idx / 162; int rem = idx - co*162;
            int ci = rem / 81,  kk = rem - ci*81;
            ws[idx] = wg[(co*64 + ci0+ci)*81 + kk];
        }
        __syncthreads();

#pragma unroll
        for (int ci = 0; ci < 2; ++ci) {
            const float* wp = ws + cq*8*162 + ci*81;
            const float* ip = ins + ci*(24*ISTR) + (ty4*4)*ISTR + tx;
            for (int ky = 0; ky < 9; ++ky) {
#pragma unroll 9
                for (int kx = 0; kx < 9; ++kx) {
                    int kk = ky*9 + kx;
                    float w8[8];
#pragma unroll
                    for (int j = 0; j < 8; ++j) w8[j] = wp[j*162 + kk];
#pragma unroll
                    for (int yy = 0; yy < 4; ++yy) {
                        float iv = ip[(yy+ky)*ISTR + kx];
#pragma unroll
                        for (int j = 0; j < 8; ++j)
                            acc[yy][j] = fmaf(iv, w8[j], acc[yy][j]);
                    }
                }
            }
        }
        __syncthreads();
    }

#pragma unroll
    for (int yy = 0; yy < 4; ++yy) {
        int y = y0 + ty4*4 + yy;
        int x = x0 + tx;
        if (y < OH && x < OH) {
#pragma unroll
            for (int j = 0; j < 8; ++j)
                out[((size_t)(n*CCH + g*32 + cq*8 + j)*OH + y)*OH + x] = acc[yy][j];
        }
    }
}

// ---------------- 3: attention per (n, g, 32-query tile) --------------------
// logits [32 x 1600] fully resident in dynamic SMEM; softmax; PV.
#define ATTN_SMEM ((32*1600 + 32*32 + 64*33) * 4)

__global__ __launch_bounds__(256)
void attn_kernel(const float* __restrict__ tau)
{
    extern __shared__ float sm[];
    float* ls = sm;                  // 32*1600 logits/probs
    float* qs = sm + 32*1600;        // [c][q] 32x32
    float* vs = qs + 1024;           // [dd][c] 64x33 (padded)

    int bz = blockIdx.x;
    int qt = bz % 72;
    int g  = (bz / 72) & 7;
    int n  = bz / 576;
    int q0 = qt * 32;

    const float* qb = g_q + ((size_t)(n*CCH) + g*32)*HWQ + q0;
    const float* kb = g_k + ((size_t)(n*CCH) + g*32)*DD;
    const float* vb = g_v + ((size_t)(n*CCH) + g*32)*DD;
    int tid = threadIdx.x;

    for (int idx = tid; idx < 1024; idx += 256) {
        int c = idx >> 5, qi = idx & 31;
        qs[idx] = qb[c*HWQ + qi];
    }
    __syncthreads();

    float tg = tau[g];

    // pass 1: S = tau * q^T k   (one d-column per thread)
    for (int dbase = 0; dbase < DD; dbase += 256) {
        int d = dbase + tid;
        if (d < DD) {
            float acc[32];
#pragma unroll
            for (int qi = 0; qi < 32; ++qi) acc[qi] = 0.f;
#pragma unroll 4
            for (int c = 0; c < 32; ++c) {
                float kc = kb[c*DD + d];
#pragma unroll
                for (int qi = 0; qi < 32; ++qi)
                    acc[qi] = fmaf(qs[c*32 + qi], kc, acc[qi]);
            }
#pragma unroll
            for (int qi = 0; qi < 32; ++qi)
                ls[qi*DD + d] = acc[qi] * tg;
        }
    }
    __syncthreads();

    // softmax: one warp per row
    int wid = tid >> 5, lane = tid & 31;
    for (int q = wid; q < 32; q += 8) {
        float* row = ls + q*DD;
        float m = -1e30f;
        for (int d = lane; d < DD; d += 32) m = fmaxf(m, row[d]);
#pragma unroll
        for (int off = 16; off; off >>= 1) m = fmaxf(m, __shfl_xor_sync(~0u, m, off));
        float s = 0.f;
        for (int d = lane; d < DD; d += 32) { float e = __expf(row[d]-m); row[d] = e; s += e; }
#pragma unroll
        for (int off = 16; off; off >>= 1) s += __shfl_xor_sync(~0u, s, off);
        float inv = 1.f / s;
        for (int d = lane; d < DD; d += 32) row[d] *= inv;
    }
    __syncthreads();

    // pass 2: A = V P^T  (thread = (c, q-strip of 4))
    int c = tid & 31, qi = tid >> 5;
    float acc[4] = {0.f, 0.f, 0.f, 0.f};
    for (int dbase = 0; dbase < DD; dbase += 64) {
        for (int idx = tid; idx < 2048; idx += 256) {
            int dd = idx & 63, cc = idx >> 6;
            vs[dd*33 + cc] = vb[cc*DD + dbase + dd];
        }
        __syncthreads();
#pragma unroll 4
        for (int dd = 0; dd < 64; ++dd) {
            float vv = vs[dd*33 + c];
#pragma unroll
            for (int t = 0; t < 4; ++t)
                acc[t] = fmaf(vv, ls[(qi + t*8)*DD + dbase + dd], acc[t]);
        }
        __syncthreads();
    }
#pragma unroll
    for (int t = 0; t < 4; ++t)
        g_a[((size_t)(n*CCH) + g*32 + c)*HWQ + q0 + qi + t*8] = acc[t];
}

// ---------------- 4: gates (grouped 1x1 on a) + cell update -----------------
__global__ __launch_bounds__(256)
void gates_kernel(const float* __restrict__ Wa_i, const float* __restrict__ Wa_f,
                  const float* __restrict__ Wa_g, const float* __restrict__ Wa_o,
                  const float* __restrict__ b_i,  const float* __restrict__ b_f,
                  const float* __restrict__ b_g,  const float* __restrict__ b_o,
                  const float* __restrict__ c_prev, float* __restrict__ out)
{
    __shared__ float ws[4][8*32];
    __shared__ float bs[4][8];
    int n  = blockIdx.z;
    int c0 = blockIdx.y * 8;
    int p0 = blockIdx.x * 256;
    int g  = c0 >> 5;
    int tid = threadIdx.x;

    if (tid < 256) {
        int j = tid >> 5, cc = tid & 31;
        ws[0][tid] = Wa_i[(c0+j)*32 + cc];
        ws[1][tid] = Wa_f[(c0+j)*32 + cc];
        ws[2][tid] = Wa_g[(c0+j)*32 + cc];
        ws[3][tid] = Wa_o[(c0+j)*32 + cc];
    }
    if (tid < 8) {
        bs[0][tid] = b_i[c0+tid]; bs[1][tid] = b_f[c0+tid];
        bs[2][tid] = b_g[c0+tid]; bs[3][tid] = b_o[c0+tid];
    }
    __syncthreads();

    int p = p0 + tid;
    const float* ab = g_a + ((size_t)(n*CCH) + g*32)*HWQ + p;

    float acc[4][8];
#pragma unroll
    for (int e = 0; e < 4; ++e)
#pragma unroll
        for (int j = 0; j < 8; ++j) acc[e][j] = 0.f;

#pragma unroll 4
    for (int cc = 0; cc < 32; ++cc) {
        float v = ab[cc*HWQ];
#pragma unroll
        for (int e = 0; e < 4; ++e)
#pragma unroll
            for (int j = 0; j < 8; ++j)
                acc[e][j] = fmaf(ws[e][j*32+cc], v, acc[e][j]);
    }

#pragma unroll
    for (int j = 0; j < 8; ++j) {
        int c = c0 + j;
        size_t off = ((size_t)(n*CCH) + c)*HWQ + p;
        float gi = sigm (acc[0][j] + g_gp[0][off] + bs[0][j]);
        float gf = sigm (acc[1][j] + g_gp[1][off] + bs[1][j]);
        float gg = tanhf(acc[2][j] + g_gp[2][off] + bs[2][j]);
        float go = sigm (acc[3][j] + g_gp[3][off] + bs[3][j]);
        float cn = gf * c_prev[off] + gi * gg;
        out[off] = go * tanhf(cn);
    }
}

// ---------------- launch ----------------------------------------------------
extern "C" void kernel_launch(void* const* d_in, const int* in_sizes, int n_in,
                              void* d_out, int out_size)
{
    (void)in_sizes; (void)n_in; (void)out_size;
    const float* inp    = (const float*)d_in[0];
    const float* h_prev = (const float*)d_in[1];
    const float* c_prev = (const float*)d_in[2];
    const float* Wx     = (const float*)d_in[3];
    const float* Wxg    = (const float*)d_in[4];
    const float* tau    = (const float*)d_in[5];
    const float* Wq     = (const float*)d_in[6];
    const float* Wk     = (const float*)d_in[7];
    const float* Wv     = (const float*)d_in[8];
    const float* Wa_i   = (const float*)d_in[9];
    const float* Wxh_i  = (const float*)d_in[10];
    const float* b_i    = (const float*)d_in[11];
    const float* Wa_f   = (const float*)d_in[12];
    const float* Wxh_f  = (const float*)d_in[13];
    const float* b_f    = (const float*)d_in[14];
    const float* Wa_g   = (const float*)d_in[15];
    const float* Wxh_g  = (const float*)d_in[16];
    const float* b_g    = (const float*)d_in[17];
    const float* Wa_o   = (const float*)d_in[18];
    const float* Wxh_o  = (const float*)d_in[19];
    const float* b_o    = (const float*)d_in[20];
    float* out = (float*)d_out;

    cudaFuncSetAttribute(attn_kernel,
                         cudaFuncAttributeMaxDynamicSharedMemorySize, ATTN_SMEM);

    proj_kernel<<<dim3(9, 32, 4), 256>>>(inp, h_prev, Wx, Wxg);
    gconv_kernel<true ><<<dim3(3, 3, 5*32), 256>>>(Wq, Wxh_i, Wxh_f, Wxh_g, Wxh_o);
    gconv_kernel<false><<<dim3(3, 3, 2*32), 256>>>(Wk, Wv, nullptr, nullptr, nullptr);
    attn_kernel<<<NN*GG*72, 256, ATTN_SMEM>>>(tau);
    gates_kernel<<<dim3(9, 32, 4), 256>>>(Wa_i, Wa_f, Wa_g, Wa_o,
                                          b_i, b_f, b_g, b_o, c_prev, out);
}

// round 3
// speedup vs baseline: 1.4561x; 1.4561x over previous
#include <cuda_runtime.h>
#include <cstdint>
#include <math.h>

// Problem constants
#define NN   4
#define II   64
#define CCH  256
#define GG   8
#define CG   32
#define KS   9
#define HH   48
#define HWQ  (48*48)   // 2304
#define HD   40
#define DD   (40*40)   // 1600
#define PW   56        // padded width/height (48 + 2*4)
#define PHW  (56*56)   // 3136

// ---------------- scratch (device globals; no allocation allowed) -----------
__device__ __align__(128) float g_xh2[NN*GG*PHW*64];  // padded channel-last xh
__device__ __align__(128) float g_wS[GG*81*160*64];   // [g][tap][row(5conv*32)][ci]
__device__ __align__(128) float g_wV[GG*81*64*64];    // [g][tap][row(2conv*32)][ci]
__device__ __align__(128) float g_q [NN*CCH*HWQ];
__device__ __align__(128) float g_k [NN*CCH*DD];
__device__ __align__(128) float g_v [NN*CCH*DD];
__device__ __align__(128) float g_a [NN*CCH*HWQ];
__device__ __align__(128) float g_gp[4][NN*CCH*HWQ];

__device__ __forceinline__ float sigm(float x) { return 1.f/(1.f+__expf(-x)); }
__device__ __forceinline__ float to_tf32(float x) {
    float r; asm("cvt.rna.tf32.f32 %0, %1;" : "=f"(r) : "f"(x)); return r;
}

// m16n8k8 tf32 mma.sync (sm_80+, valid on base sm_103 target)
__device__ __forceinline__ void mma8(float* c, const uint32_t* a,
                                     uint32_t b0, uint32_t b1) {
    asm volatile(
        "mma.sync.aligned.m16n8k8.row.col.f32.tf32.tf32.f32 "
        "{%0,%1,%2,%3}, {%4,%5,%6,%7}, {%8,%9}, {%0,%1,%2,%3};"
        : "+f"(c[0]), "+f"(c[1]), "+f"(c[2]), "+f"(c[3])
        : "r"(a[0]), "r"(a[1]), "r"(a[2]), "r"(a[3]), "r"(b0), "r"(b1));
}

// ---------------- 0: zero padded xh buffer ----------------------------------
__global__ void zero_xh2_kernel() {
    size_t total4 = (size_t)NN*GG*PHW*64/4;
    float4* p = reinterpret_cast<float4*>(g_xh2);
    for (size_t i = (size_t)blockIdx.x*blockDim.x + threadIdx.x; i < total4;
         i += (size_t)gridDim.x*blockDim.x)
        p[i] = make_float4(0.f,0.f,0.f,0.f);
}

// ---------------- 0b: weight transpose (+ tf32 rna pre-round) ---------------
__global__ void wtrans_kernel(const float* __restrict__ Wq, const float* __restrict__ Wi,
                              const float* __restrict__ Wf, const float* __restrict__ Wg,
                              const float* __restrict__ Wo, const float* __restrict__ Wk,
                              const float* __restrict__ Wv)
{
    const int total_s = GG*81*160*64;
    const int total_v = GG*81*64*64;
    for (int o = blockIdx.x*blockDim.x + threadIdx.x; o < total_s + total_v;
         o += gridDim.x*blockDim.x) {
        if (o < total_s) {
            int ci = o & 63;
            int r  = (o >> 6) % 160;
            int k  = ((o >> 6) / 160) % 81;
            int g  = o / (64*160*81);
            int j = r >> 5, co = r & 31;
            const float* W = (j==0)?Wq:(j==1)?Wi:(j==2)?Wf:(j==3)?Wg:Wo;
            g_wS[o] = to_tf32(W[((size_t)(g*32+co)*64 + ci)*81 + k]);
        } else {
            int o2 = o - total_s;
            int ci = o2 & 63;
            int r  = (o2 >> 6) & 63;
            int k  = ((o2 >> 6) >> 6) % 81;
            int g  = o2 / (64*64*81);
            const float* W = (r < 32) ? Wk : Wv;
            g_wV[o2] = to_tf32(W[((size_t)(g*32+(r&31))*64 + ci)*81 + k]);
        }
    }
}

// ---------------- 1: projection + build padded channel-last xh --------------
__global__ __launch_bounds__(256)
void proj_kernel(const float* __restrict__ inp, const float* __restrict__ h,
                 const float* __restrict__ Wx, const float* __restrict__ Wxg)
{
    __shared__ float ws[8*320];
    int n  = blockIdx.z;
    int c0 = blockIdx.y * 8;
    int p0 = blockIdx.x * 256;
    int tid = threadIdx.x;

    for (int idx = tid; idx < 8*320; idx += 256) {
        int j = idx / 320, ic = idx - j*320;
        ws[idx] = (ic < 64) ? Wx[(c0+j)*64 + ic] : Wxg[(c0+j)*256 + (ic-64)];
    }
    __syncthreads();

    int p = p0 + tid;
    float acc[8];
#pragma unroll
    for (int j = 0; j < 8; ++j) acc[j] = 0.f;

    const float* ib = inp + (size_t)n*II*HWQ + p;
    const float* hb = h   + (size_t)n*CCH*HWQ + p;

#pragma unroll 4
    for (int ic = 0; ic < 64; ++ic) {
        float v = ib[ic*HWQ];
#pragma unroll
        for (int j = 0; j < 8; ++j) acc[j] = fmaf(ws[j*320+ic], v, acc[j]);
    }
#pragma unroll 4
    for (int ic = 0; ic < 256; ++ic) {
        float v = hb[ic*HWQ];
#pragma unroll
        for (int j = 0; j < 8; ++j) acc[j] = fmaf(ws[j*320+64+ic], v, acc[j]);
    }

    int y = p / 48, x = p - y*48;
    int g = c0 >> 5;
    float* xb = g_xh2 + ((size_t)(n*GG + g)*PHW + (y+4)*PW + (x+4))*64;
#pragma unroll
    for (int j = 0; j < 8; ++j) {
        int cg = (c0 + j) & 31;
        xb[cg]      = to_tf32(acc[j]);
        xb[32 + cg] = to_tf32(hb[(c0+j)*HWQ]);
    }
}

// ---------------- 2: grouped KxK conv via mma.sync tf32 ---------------------
// D[128 spatial, NC out] = im2col(A) x W^T. Block 256 thr = 8 warps (4M x 2N).
// Warp tile 32M x (NC/2)N.  SAME: NC=160 (q,i,f,g,o).  VALID: NC=64 (k,v).
template<int NC, int BASE, int OW, int TN>
__global__ __launch_bounds__(256)
void conv_mma_kernel()
{
    extern __shared__ float smf[];
    constexpr int ASZ = 32*132;          // A buffer: [k 32][m 128 pad 132]
    constexpr int BSZ = 32*(NC+4);       // B buffer: [k 32][n NC pad NC+4]
    float* Abuf[2] = { smf, smf + ASZ };
    float* Bbuf[2] = { smf + 2*ASZ, smf + 2*ASZ + BSZ };

    const int tid = threadIdx.x;
    const int wid = tid >> 5, lane = tid & 31;
    const int gid = lane >> 2, tig = lane & 3;
    const int mb  = (wid >> 1) * 32;
    const int nb  = (wid & 1) * (NC/2);

    const int g  = blockIdx.y;
    const int n  = blockIdx.z;
    const int x0 = (blockIdx.x % 3) * 16;
    const int y0 = (blockIdx.x / 3) * 8;

    float* outs[5];
    if (NC == 160) { outs[0]=g_q; outs[1]=g_gp[0]; outs[2]=g_gp[1]; outs[3]=g_gp[2]; outs[4]=g_gp[3]; }
    else           { outs[0]=g_k; outs[1]=g_v; outs[2]=nullptr; outs[3]=nullptr; outs[4]=nullptr; }

    const float* xsrc = g_xh2 + (size_t)(n*GG + g)*PHW*64;
    const float* wg   = ((NC == 160) ? g_wS : g_wV) + (size_t)g*81*NC*64;

    float acc[2][TN][4];
#pragma unroll
    for (int mi = 0; mi < 2; ++mi)
#pragma unroll
        for (int nj = 0; nj < TN; ++nj)
#pragma unroll
            for (int r = 0; r < 4; ++r) acc[mi][nj][r] = 0.f;

    auto stage = [&](int t, int buf) {
        int kk = t >> 1, ci0 = (t & 1) * 32;
        int ky = kk / 9, kx = kk - ky*9;
        float* As = Abuf[buf];
        float* Bs = Bbuf[buf];
        const float* abase = xsrc + (size_t)((y0 + BASE + ky)*PW + (x0 + BASE + kx))*64 + ci0;
        // A: 128 positions x 32 floats -> transposed [k][m]; conflict-free STS
        for (int u = tid; u < 1024; u += 256) {
            int m = u & 127, f4 = u >> 7;
            int ty = m >> 4, tx = m & 15;
            float4 v = *reinterpret_cast<const float4*>(abase + (ty*PW + tx)*64 + f4*4);
            int k = f4*4;
            As[(k+0)*132 + m] = v.x; As[(k+1)*132 + m] = v.y;
            As[(k+2)*132 + m] = v.z; As[(k+3)*132 + m] = v.w;
        }
        // B: NC rows x 32 floats -> [k][n]
        const float* wchunk = wg + (size_t)kk*NC*64 + ci0;
#pragma unroll
        for (int f4 = 0; f4 < 8; ++f4) {
            for (int nn2 = tid; nn2 < NC; nn2 += 256) {
                float4 v = *reinterpret_cast<const float4*>(wchunk + nn2*64 + f4*4);
                int k = f4*4;
                Bs[(k+0)*(NC+4) + nn2] = v.x; Bs[(k+1)*(NC+4) + nn2] = v.y;
                Bs[(k+2)*(NC+4) + nn2] = v.z; Bs[(k+3)*(NC+4) + nn2] = v.w;
            }
        }
    };

    stage(0, 0);
    __syncthreads();

    for (int t = 0; t < 162; ++t) {
        int buf = t & 1;
        if (t + 1 < 162) stage(t + 1, buf ^ 1);
        const float* As = Abuf[buf];
        const float* Bs = Bbuf[buf];
#pragma unroll
        for (int ks = 0; ks < 4; ++ks) {
            int k = ks*8 + tig;
            const float* a0p = As + k*132 + mb;
            const float* a4p = a0p + 4*132;
            uint32_t a[2][4];
#pragma unroll
            for (int mi = 0; mi < 2; ++mi) {
                a[mi][0] = __float_as_uint(a0p[mi*16 + gid]);
                a[mi][1] = __float_as_uint(a0p[mi*16 + gid + 8]);
                a[mi][2] = __float_as_uint(a4p[mi*16 + gid]);
                a[mi][3] = __float_as_uint(a4p[mi*16 + gid + 8]);
            }
            const float* b0p = Bs + k*(NC+4) + nb;
            const float* b4p = b0p + 4*(NC+4);
#pragma unroll
            for (int nj = 0; nj < TN; ++nj) {
                uint32_t b0 = __float_as_uint(b0p[nj*8 + gid]);
                uint32_t b1 = __float_as_uint(b4p[nj*8 + gid]);
                mma8(acc[0][nj], a[0], b0, b1);
                mma8(acc[1][nj], a[1], b0, b1);
            }
        }
        __syncthreads();
    }

    // epilogue
#pragma unroll
    for (int mi = 0; mi < 2; ++mi)
#pragma unroll
        for (int nj = 0; nj < TN; ++nj)
#pragma unroll
            for (int r = 0; r < 4; ++r) {
                int m = mb + mi*16 + gid + ((r >> 1) << 3);
                int nc = nb + nj*8 + tig*2 + (r & 1);
                int y = y0 + (m >> 4), x = x0 + (m & 15);
                if (y < OW && x < OW) {
                    int conv = nc >> 5, cg = nc & 31;
                    outs[conv][((size_t)(n*CCH + g*32 + cg)*OW + y)*OW + x] = acc[mi][nj][r];
                }
            }
}

// ---------------- 3: attention per (n, g, 16-query tile) --------------------
#define QT 16
#define ATTN_SMEM ((QT*DD + 32*QT + 64*33) * 4)

__global__ __launch_bounds__(256)
void attn_kernel(const float* __restrict__ tau)
{
    extern __shared__ float smf[];
    float* ls = smf;                 // QT x 1600 logits/probs
    float* qs = smf + QT*DD;         // [c 32][q 16]
    float* vs = qs + 32*QT;          // [dd 64][c 32] pad 33

    int bz = blockIdx.x;
    int qt = bz % 144;
    int g  = (bz / 144) & 7;
    int n  = bz / 1152;
    int q0 = qt * QT;

    const float* qb = g_q + ((size_t)(n*CCH) + g*32)*HWQ + q0;
    const float* kb = g_k + ((size_t)(n*CCH) + g*32)*DD;
    const float* vb = g_v + ((size_t)(n*CCH) + g*32)*DD;
    int tid = threadIdx.x;

    for (int idx = tid; idx < 32*QT; idx += 256) {
        int c = idx >> 4, qi = idx & 15;
        qs[idx] = qb[c*HWQ + qi];
    }
    __syncthreads();

    float tg = tau[g];

    // pass 1: S = tau * q^T k  (one d-column per thread; q reads via LDS.128)
    for (int dbase = 0; dbase < DD; dbase += 256) {
        int d = dbase + tid;
        if (d < DD) {
            float acc[QT];
#pragma unroll
            for (int qi = 0; qi < QT; ++qi) acc[qi] = 0.f;
#pragma unroll 2
            for (int c = 0; c < 32; ++c) {
                float kc = kb[c*DD + d];
                const float4* q4 = reinterpret_cast<const float4*>(qs + c*QT);
#pragma unroll
                for (int v4 = 0; v4 < QT/4; ++v4) {
                    float4 q = q4[v4];
                    acc[v4*4+0] = fmaf(q.x, kc, acc[v4*4+0]);
                    acc[v4*4+1] = fmaf(q.y, kc, acc[v4*4+1]);
                    acc[v4*4+2] = fmaf(q.z, kc, acc[v4*4+2]);
                    acc[v4*4+3] = fmaf(q.w, kc, acc[v4*4+3]);
                }
            }
#pragma unroll
            for (int qi = 0; qi < QT; ++qi)
                ls[qi*DD + d] = acc[qi] * tg;
        }
    }
    __syncthreads();

    // softmax: one warp per row
    int wid = tid >> 5, lane = tid & 31;
    for (int q = wid; q < QT; q += 8) {
        float* row = ls + q*DD;
        float m = -1e30f;
        for (int d = lane; d < DD; d += 32) m = fmaxf(m, row[d]);
#pragma unroll
        for (int off = 16; off; off >>= 1) m = fmaxf(m, __shfl_xor_sync(~0u, m, off));
        float s = 0.f;
        for (int d = lane; d < DD; d += 32) { float e = __expf(row[d]-m); row[d] = e; s += e; }
#pragma unroll
        for (int off = 16; off; off >>= 1) s += __shfl_xor_sync(~0u, s, off);
        float inv = 1.f / s;
        for (int d = lane; d < DD; d += 32) row[d] *= inv;
    }
    __syncthreads();

    // pass 2: A = V P^T  (thread = (c, q-strip of 2))
    int c = tid & 31, qi = tid >> 5;
    float acc[2] = {0.f, 0.f};
    for (int dbase = 0; dbase < DD; dbase += 64) {
        for (int idx = tid; idx < 2048; idx += 256) {
            int dd = idx & 63, cc = idx >> 6;
            vs[dd*33 + cc] = vb[cc*DD + dbase + dd];
        }
        __syncthreads();
#pragma unroll 8
        for (int dd = 0; dd < 64; dd += 2) {
            float vv0 = vs[dd*33 + c];
            float vv1 = vs[(dd+1)*33 + c];
#pragma unroll
            for (int t = 0; t < 2; ++t) {
                float2 w = *reinterpret_cast<const float2*>(ls + (qi + t*8)*DD + dbase + dd);
                acc[t] = fmaf(vv0, w.x, acc[t]);
                acc[t] = fmaf(vv1, w.y, acc[t]);
            }
        }
        __syncthreads();
    }
#pragma unroll
    for (int t = 0; t < 2; ++t)
        g_a[((size_t)(n*CCH) + g*32 + c)*HWQ + q0 + qi + t*8] = acc[t];
}

// ---------------- 4: gates (grouped 1x1 on a) + cell update -----------------
__global__ __launch_bounds__(256)
void gates_kernel(const float* __restrict__ Wa_i, const float* __restrict__ Wa_f,
                  const float* __restrict__ Wa_g, const float* __restrict__ Wa_o,
                  const float* __restrict__ b_i,  const float* __restrict__ b_f,
                  const float* __restrict__ b_g,  const float* __restrict__ b_o,
                  const float* __restrict__ c_prev, float* __restrict__ out)
{
    __shared__ float ws[4][8*32];
    __shared__ float bs[4][8];
    int n  = blockIdx.z;
    int c0 = blockIdx.y * 8;
    int p0 = blockIdx.x * 256;
    int g  = c0 >> 5;
    int tid = threadIdx.x;

    {
        int j = tid >> 5, cc = tid & 31;
        ws[0][tid] = Wa_i[(c0+j)*32 + cc];
        ws[1][tid] = Wa_f[(c0+j)*32 + cc];
        ws[2][tid] = Wa_g[(c0+j)*32 + cc];
        ws[3][tid] = Wa_o[(c0+j)*32 + cc];
    }
    if (tid < 8) {
        bs[0][tid] = b_i[c0+tid]; bs[1][tid] = b_f[c0+tid];
        bs[2][tid] = b_g[c0+tid]; bs[3][tid] = b_o[c0+tid];
    }
    __syncthreads();

    int p = p0 + tid;
    const float* ab = g_a + ((size_t)(n*CCH) + g*32)*HWQ + p;

    float acc[4][8];
#pragma unroll
    for (int e = 0; e < 4; ++e)
#pragma unroll
        for (int j = 0; j < 8; ++j) acc[e][j] = 0.f;

#pragma unroll 4
    for (int cc = 0; cc < 32; ++cc) {
        float v = ab[cc*HWQ];
#pragma unroll
        for (int e = 0; e < 4; ++e)
#pragma unroll
            for (int j = 0; j < 8; ++j)
                acc[e][j] = fmaf(ws[e][j*32+cc], v, acc[e][j]);
    }

#pragma unroll
    for (int j = 0; j < 8; ++j) {
        int c = c0 + j;
        size_t off = ((size_t)(n*CCH) + c)*HWQ + p;
        float gi = sigm (acc[0][j] + g_gp[0][off] + bs[0][j]);
        float gf = sigm (acc[1][j] + g_gp[1][off] + bs[1][j]);
        float gg = tanhf(acc[2][j] + g_gp[2][off] + bs[2][j]);
        float go = sigm (acc[3][j] + g_gp[3][off] + bs[3][j]);
        float cn = gf * c_prev[off] + gi * gg;
        out[off] = go * tanhf(cn);
    }
}

// ---------------- launch ----------------------------------------------------
extern "C" void kernel_launch(void* const* d_in, const int* in_sizes, int n_in,
                              void* d_out, int out_size)
{
    (void)in_sizes; (void)n_in; (void)out_size;
    const float* inp    = (const float*)d_in[0];
    const float* h_prev = (const float*)d_in[1];
    const float* c_prev = (const float*)d_in[2];
    const float* Wx     = (const float*)d_in[3];
    const float* Wxg    = (const float*)d_in[4];
    const float* tau    = (const float*)d_in[5];
    const float* Wq     = (const float*)d_in[6];
    const float* Wk     = (const float*)d_in[7];
    const float* Wv     = (const float*)d_in[8];
    const float* Wa_i   = (const float*)d_in[9];
    const float* Wxh_i  = (const float*)d_in[10];
    const float* b_i    = (const float*)d_in[11];
    const float* Wa_f   = (const float*)d_in[12];
    const float* Wxh_f  = (const float*)d_in[13];
    const float* b_f    = (const float*)d_in[14];
    const float* Wa_g   = (const float*)d_in[15];
    const float* Wxh_g  = (const float*)d_in[16];
    const float* b_g    = (const float*)d_in[17];
    const float* Wa_o   = (const float*)d_in[18];
    const float* Wxh_o  = (const float*)d_in[19];
    const float* b_o    = (const float*)d_in[20];
    float* out = (float*)d_out;

    const int SMEM_S = (2*32*132 + 2*32*164) * 4;   // 75776
    const int SMEM_V = (2*32*132 + 2*32*68)  * 4;   // 51200

    cudaFuncSetAttribute(attn_kernel,
                         cudaFuncAttributeMaxDynamicSharedMemorySize, ATTN_SMEM);
    cudaFuncSetAttribute(conv_mma_kernel<160,0,48,10>,
                         cudaFuncAttributeMaxDynamicSharedMemorySize, SMEM_S);
    cudaFuncSetAttribute(conv_mma_kernel<64,4,40,4>,
                         cudaFuncAttributeMaxDynamicSharedMemorySize, SMEM_V);

    zero_xh2_kernel<<<2048, 256>>>();
    wtrans_kernel<<<4096, 256>>>(Wq, Wxh_i, Wxh_f, Wxh_g, Wxh_o, Wk, Wv);
    proj_kernel<<<dim3(9, 32, 4), 256>>>(inp, h_prev, Wx, Wxg);
    conv_mma_kernel<160,0,48,10><<<dim3(18, 8, 4), 256, SMEM_S>>>();
    conv_mma_kernel<64,4,40,4><<<dim3(15, 8, 4), 256, SMEM_V>>>();
    attn_kernel<<<NN*GG*144, 256, ATTN_SMEM>>>(tau);
    gates_kernel<<<dim3(9, 32, 4), 256>>>(Wa_i, Wa_f, Wa_g, Wa_o,
                                          b_i, b_f, b_g, b_o, c_prev, out);
}

// round 4
// speedup vs baseline: 2.6657x; 1.8307x over previous
#include <cuda_runtime.h>
#include <cstdint>
#include <math.h>

// Problem constants
#define NN   4
#define II   64
#define CCH  256
#define GG   8
#define CG   32
#define KS   9
#define HH   48
#define HWQ  (48*48)   // 2304
#define HD   40
#define DD   (40*40)   // 1600
#define PW   56        // padded width/height (48 + 2*4)
#define PHW  (56*56)   // 3136

// ---------------- scratch (device globals; no allocation allowed) -----------
__device__ __align__(128) float g_xh2[NN*GG*PHW*64];  // padded channel-last xh
__device__ __align__(128) float g_wS[GG*81*160*64];   // [g][tap][row(5conv*32)][ci]
__device__ __align__(128) float g_wV[GG*81*64*64];    // [g][tap][row(2conv*32)][ci]
__device__ __align__(128) float g_q [NN*CCH*HWQ];
__device__ __align__(128) float g_k [NN*CCH*DD];
__device__ __align__(128) float g_v [NN*CCH*DD];
__device__ __align__(128) float g_a [NN*CCH*HWQ];
__device__ __align__(128) float g_gp[4][NN*CCH*HWQ];

__device__ __forceinline__ float to_tf32(float x) {
    float r; asm("cvt.rna.tf32.f32 %0, %1;" : "=f"(r) : "f"(x)); return r;
}
// FFMA-only exp for x <= 0 (softmax): e^x = 2^(x*log2e), magic-number split.
__device__ __forceinline__ float fastexp(float x) {
    float z = fmaxf(x * 1.4426950408889634f, -120.f);
    float t = z + 12582912.f;                    // round-to-int in mantissa
    int   e = __float_as_int(t) - 0x4B400000;    // integer part (signed)
    float f = z - (t - 12582912.f);              // frac in [-0.5, 0.5]
    float p = fmaf(f, 0.0013333558f, 0.0096181291f);
    p = fmaf(f, p, 0.0555041087f);
    p = fmaf(f, p, 0.2402265069f);
    p = fmaf(f, p, 0.69314718056f);
    p = fmaf(f, p, 1.0f);
    return __int_as_float(__float_as_int(p) + (e << 23));
}
__device__ __forceinline__ float ftanh(float x) {
    float t; asm("tanh.approx.f32 %0, %1;" : "=f"(t) : "f"(x)); return t;
}
__device__ __forceinline__ float sigm(float x) {
    return fmaf(ftanh(x * 0.5f), 0.5f, 0.5f);
}

// m16n8k8 tf32 mma.sync
__device__ __forceinline__ void mma8(float* c, const uint32_t* a,
                                     uint32_t b0, uint32_t b1) {
    asm volatile(
        "mma.sync.aligned.m16n8k8.row.col.f32.tf32.tf32.f32 "
        "{%0,%1,%2,%3}, {%4,%5,%6,%7}, {%8,%9}, {%0,%1,%2,%3};"
        : "+f"(c[0]), "+f"(c[1]), "+f"(c[2]), "+f"(c[3])
        : "r"(a[0]), "r"(a[1]), "r"(a[2]), "r"(a[3]), "r"(b0), "r"(b1));
}
__device__ __forceinline__ void cp16(uint32_t dst, const void* src) {
    asm volatile("cp.async.cg.shared.global [%0], [%1], 16;" :: "r"(dst), "l"(src));
}
__device__ __forceinline__ uint32_t smem_u32(const void* p) {
    uint32_t a;
    asm("{ .reg .u64 t; cvta.to.shared.u64 t, %1; cvt.u32.u64 %0, t; }" : "=r"(a) : "l"(p));
    return a;
}

// ---------------- 0: zero padded xh buffer ----------------------------------
__global__ void zero_xh2_kernel() {
    size_t total4 = (size_t)NN*GG*PHW*64/4;
    float4* p = reinterpret_cast<float4*>(g_xh2);
    for (size_t i = (size_t)blockIdx.x*blockDim.x + threadIdx.x; i < total4;
         i += (size_t)gridDim.x*blockDim.x)
        p[i] = make_float4(0.f,0.f,0.f,0.f);
}

// ---------------- 0b: weight transpose (+ tf32 rna pre-round) ---------------
__global__ void wtrans_kernel(const float* __restrict__ Wq, const float* __restrict__ Wi,
                              const float* __restrict__ Wf, const float* __restrict__ Wg,
                              const float* __restrict__ Wo, const float* __restrict__ Wk,
                              const float* __restrict__ Wv)
{
    const int total_s = GG*81*160*64;
    const int total_v = GG*81*64*64;
    for (int o = blockIdx.x*blockDim.x + threadIdx.x; o < total_s + total_v;
         o += gridDim.x*blockDim.x) {
        if (o < total_s) {
            int ci = o & 63;
            int r  = (o >> 6) % 160;
            int k  = ((o >> 6) / 160) % 81;
            int g  = o / (64*160*81);
            int j = r >> 5, co = r & 31;
            const float* W = (j==0)?Wq:(j==1)?Wi:(j==2)?Wf:(j==3)?Wg:Wo;
            g_wS[o] = to_tf32(W[((size_t)(g*32+co)*64 + ci)*81 + k]);
        } else {
            int o2 = o - total_s;
            int ci = o2 & 63;
            int r  = (o2 >> 6) & 63;
            int k  = ((o2 >> 6) >> 6) % 81;
            int g  = o2 / (64*64*81);
            const float* W = (r < 32) ? Wk : Wv;
            g_wV[o2] = to_tf32(W[((size_t)(g*32+(r&31))*64 + ci)*81 + k]);
        }
    }
}

// ---------------- 1: projection + build padded channel-last xh --------------
__global__ __launch_bounds__(256)
void proj_kernel(const float* __restrict__ inp, const float* __restrict__ h,
                 const float* __restrict__ Wx, const float* __restrict__ Wxg)
{
    __shared__ float ws[8*320];
    int n  = blockIdx.z;
    int c0 = blockIdx.y * 8;
    int p0 = blockIdx.x * 256;
    int tid = threadIdx.x;

    for (int idx = tid; idx < 8*320; idx += 256) {
        int j = idx / 320, ic = idx - j*320;
        ws[idx] = (ic < 64) ? Wx[(c0+j)*64 + ic] : Wxg[(c0+j)*256 + (ic-64)];
    }
    __syncthreads();

    int p = p0 + tid;
    float acc[8];
#pragma unroll
    for (int j = 0; j < 8; ++j) acc[j] = 0.f;

    const float* ib = inp + (size_t)n*II*HWQ + p;
    const float* hb = h   + (size_t)n*CCH*HWQ + p;

#pragma unroll 4
    for (int ic = 0; ic < 64; ++ic) {
        float v = ib[ic*HWQ];
#pragma unroll
        for (int j = 0; j < 8; ++j) acc[j] = fmaf(ws[j*320+ic], v, acc[j]);
    }
#pragma unroll 4
    for (int ic = 0; ic < 256; ++ic) {
        float v = hb[ic*HWQ];
#pragma unroll
        for (int j = 0; j < 8; ++j) acc[j] = fmaf(ws[j*320+64+ic], v, acc[j]);
    }

    int y = p / 48, x = p - y*48;
    int g = c0 >> 5;
    float* xb = g_xh2 + ((size_t)(n*GG + g)*PHW + (y+4)*PW + (x+4))*64;
#pragma unroll
    for (int j = 0; j < 8; ++j) {
        int cg = (c0 + j) & 31;
        xb[cg]      = to_tf32(acc[j]);
        xb[32 + cg] = to_tf32(hb[(c0+j)*HWQ]);
    }
}

// ---------------- 2: grouped KxK conv via mma.sync tf32 ---------------------
// Block: 256 spatial (16y x 16x) x NC outs.  8 warps = 4 Mwarps x 2 Nwarps.
// Warp tile 64M x (NC/2)N.  Persistent input tile [24][24][68] in SMEM;
// B chunks [NC][36] double-buffered via cp.async.
#define ITSZ (24*24*68)     // 39168 floats
template<int NC, int BASE, int OW, int TN>
__global__ __launch_bounds__(256, 1)
void conv_mma_kernel()
{
    extern __shared__ float smf[];
    float* IT = smf;

    const int tid = threadIdx.x;
    const int wid = tid >> 5, lane = tid & 31;
    const int gid = lane >> 2, tig = lane & 3;
    const int my0 = (wid >> 1) * 4;          // warp's first output row (of 16)
    const int nb  = (wid & 1) * (NC/2);

    const int g  = blockIdx.y;
    const int n  = blockIdx.z;
    const int x0 = (blockIdx.x % 3) * 16;
    const int y0 = (blockIdx.x / 3) * 16;

    float* outs[5];
    if (NC == 160) { outs[0]=g_q; outs[1]=g_gp[0]; outs[2]=g_gp[1]; outs[3]=g_gp[2]; outs[4]=g_gp[3]; }
    else           { outs[0]=g_k; outs[1]=g_v; outs[2]=nullptr; outs[3]=nullptr; outs[4]=nullptr; }

    const float* xsrc = g_xh2 + (size_t)(n*GG + g)*PHW*64;
    const float* wg   = ((NC == 160) ? g_wS : g_wV) + (size_t)g*81*NC*64;
    const uint32_t smemB = smem_u32(smf) + ITSZ*4;

    auto stageB = [&](int t, int buf) {
        int kk = t >> 1, ci0 = (t & 1) * 32;
        const float* wsrc = wg + (size_t)kk*NC*64 + ci0;
        uint32_t bbase = smemB + (uint32_t)buf*(NC*36*4);
        for (int u = tid; u < NC*8; u += 256) {
            int n2 = u >> 3, seg = u & 7;
            cp16(bbase + (uint32_t)(n2*36 + seg*4)*4, wsrc + n2*64 + seg*4);
        }
    };

    // prologue: stage B chunk 0, then the persistent input tile
    stageB(0, 0);
    asm volatile("cp.async.commit_group;" ::: "memory");
    for (int u = tid; u < 24*24*16; u += 256) {
        int f4 = u & 15, pos = u >> 4;
        int yy = pos / 24, xx = pos - yy*24;
        int gy = min(y0 + BASE + yy, 55), gx = min(x0 + BASE + xx, 55);
        float4 v = *reinterpret_cast<const float4*>(xsrc + (size_t)(gy*PW + gx)*64 + f4*4);
        *reinterpret_cast<float4*>(IT + (yy*24 + xx)*68 + f4*4) = v;
    }

    float acc[4][TN][4];
#pragma unroll
    for (int mi = 0; mi < 4; ++mi)
#pragma unroll
        for (int nj = 0; nj < TN; ++nj)
#pragma unroll
            for (int r = 0; r < 4; ++r) acc[mi][nj][r] = 0.f;

    asm volatile("cp.async.wait_group 0;" ::: "memory");
    __syncthreads();

    for (int t = 0; t < 162; ++t) {
        if (t + 1 < 162) {
            stageB(t+1, (t+1) & 1);
            asm volatile("cp.async.commit_group;" ::: "memory");
            asm volatile("cp.async.wait_group 1;" ::: "memory");
        } else {
            asm volatile("cp.async.wait_group 0;" ::: "memory");
        }
        __syncthreads();

        const int kk = t >> 1, ci0 = (t & 1) * 32;
        const int ky = kk / 9, kx = kk - ky*9;
        const float* Bsp = smf + ITSZ + (t & 1)*(NC*36);

#pragma unroll
        for (int ks = 0; ks < 4; ++ks) {
            const int kb = ks*8 + tig;
            uint32_t a[4][4];
#pragma unroll
            for (int mi = 0; mi < 4; ++mi) {
                const float* p = IT + ((my0 + mi + ky)*24 + kx + gid)*68 + ci0 + kb;
                a[mi][0] = __float_as_uint(p[0]);
                a[mi][1] = __float_as_uint(p[544]);
                a[mi][2] = __float_as_uint(p[4]);
                a[mi][3] = __float_as_uint(p[548]);
            }
#pragma unroll
            for (int nj = 0; nj < TN; ++nj) {
                const float* bp = Bsp + (nb + nj*8 + gid)*36 + kb;
                uint32_t b0 = __float_as_uint(bp[0]);
                uint32_t b1 = __float_as_uint(bp[4]);
#pragma unroll
                for (int mi = 0; mi < 4; ++mi)
                    mma8(acc[mi][nj], a[mi], b0, b1);
            }
        }
        __syncthreads();
    }

    // epilogue
#pragma unroll
    for (int mi = 0; mi < 4; ++mi) {
        int y = y0 + my0 + mi;
        if (y >= OW) continue;
#pragma unroll
        for (int nj = 0; nj < TN; ++nj)
#pragma unroll
            for (int r = 0; r < 4; ++r) {
                int x = x0 + gid + ((r >> 1) << 3);
                if (x < OW) {
                    int nc = nb + nj*8 + tig*2 + (r & 1);
                    int conv = nc >> 5, cg = nc & 31;
                    outs[conv][((size_t)(n*CCH + g*32 + cg)*OW + y)*OW + x] = acc[mi][nj][r];
                }
            }
    }
}

// ---------------- 3: attention per (n, g, 16-query tile) --------------------
#define QT 16
#define ATTN_SMEM ((QT*DD + 32*QT + 64*33) * 4)

__global__ __launch_bounds__(256)
void attn_kernel(const float* __restrict__ tau)
{
    extern __shared__ float smf[];
    float* ls = smf;                 // QT x 1600 logits/probs
    float* qs = smf + QT*DD;         // [c 32][q 16]
    float* vs = qs + 32*QT;          // [dd 64][c 32] pad 33

    int bz = blockIdx.x;
    int qt = bz % 144;
    int g  = (bz / 144) & 7;
    int n  = bz / 1152;
    int q0 = qt * QT;

    const float* qb = g_q + ((size_t)(n*CCH) + g*32)*HWQ + q0;
    const float* kb = g_k + ((size_t)(n*CCH) + g*32)*DD;
    const float* vb = g_v + ((size_t)(n*CCH) + g*32)*DD;
    int tid = threadIdx.x;

    for (int idx = tid; idx < 32*QT; idx += 256) {
        int c = idx >> 4, qi = idx & 15;
        qs[idx] = qb[c*HWQ + qi];
    }
    __syncthreads();

    float tg = tau[g];

    // pass 1: S = tau * q^T k
    for (int dbase = 0; dbase < DD; dbase += 256) {
        int d = dbase + tid;
        if (d < DD) {
            float acc[QT];
#pragma unroll
            for (int qi = 0; qi < QT; ++qi) acc[qi] = 0.f;
#pragma unroll 2
            for (int c = 0; c < 32; ++c) {
                float kc = kb[c*DD + d];
                const float4* q4 = reinterpret_cast<const float4*>(qs + c*QT);
#pragma unroll
                for (int v4 = 0; v4 < QT/4; ++v4) {
                    float4 q = q4[v4];
                    acc[v4*4+0] = fmaf(q.x, kc, acc[v4*4+0]);
                    acc[v4*4+1] = fmaf(q.y, kc, acc[v4*4+1]);
                    acc[v4*4+2] = fmaf(q.z, kc, acc[v4*4+2]);
                    acc[v4*4+3] = fmaf(q.w, kc, acc[v4*4+3]);
                }
            }
#pragma unroll
            for (int qi = 0; qi < QT; ++qi)
                ls[qi*DD + d] = acc[qi] * tg;
        }
    }
    __syncthreads();

    // softmax: one warp per row, FFMA-only exp
    int wid = tid >> 5, lane = tid & 31;
    for (int q = wid; q < QT; q += 8) {
        float* row = ls + q*DD;
        float m = -1e30f;
        for (int d = lane; d < DD; d += 32) m = fmaxf(m, row[d]);
#pragma unroll
        for (int off = 16; off; off >>= 1) m = fmaxf(m, __shfl_xor_sync(~0u, m, off));
        float s = 0.f;
        for (int d = lane; d < DD; d += 32) { float e = fastexp(row[d]-m); row[d] = e; s += e; }
#pragma unroll
        for (int off = 16; off; off >>= 1) s += __shfl_xor_sync(~0u, s, off);
        float inv = 1.f / s;
        for (int d = lane; d < DD; d += 32) row[d] *= inv;
    }
    __syncthreads();

    // pass 2: A = V P^T
    int c = tid & 31, qi = tid >> 5;
    float acc[2] = {0.f, 0.f};
    for (int dbase = 0; dbase < DD; dbase += 64) {
        for (int idx = tid; idx < 2048; idx += 256) {
            int dd = idx & 63, cc = idx >> 6;
            vs[dd*33 + cc] = vb[cc*DD + dbase + dd];
        }
        __syncthreads();
#pragma unroll 8
        for (int dd = 0; dd < 64; dd += 2) {
            float vv0 = vs[dd*33 + c];
            float vv1 = vs[(dd+1)*33 + c];
#pragma unroll
            for (int t = 0; t < 2; ++t) {
                float2 w = *reinterpret_cast<const float2*>(ls + (qi + t*8)*DD + dbase + dd);
                acc[t] = fmaf(vv0, w.x, acc[t]);
                acc[t] = fmaf(vv1, w.y, acc[t]);
            }
        }
        __syncthreads();
    }
#pragma unroll
    for (int t = 0; t < 2; ++t)
        g_a[((size_t)(n*CCH) + g*32 + c)*HWQ + q0 + qi + t*8] = acc[t];
}

// ---------------- 4: gates (grouped 1x1 on a) + cell update -----------------
__global__ __launch_bounds__(256)
void gates_kernel(const float* __restrict__ Wa_i, const float* __restrict__ Wa_f,
                  const float* __restrict__ Wa_g, const float* __restrict__ Wa_o,
                  const float* __restrict__ b_i,  const float* __restrict__ b_f,
                  const float* __restrict__ b_g,  const float* __restrict__ b_o,
                  const float* __restrict__ c_prev, float* __restrict__ out)
{
    __shared__ float ws[4][8*32];
    __shared__ float bs[4][8];
    int n  = blockIdx.z;
    int c0 = blockIdx.y * 8;
    int p0 = blockIdx.x * 256;
    int g  = c0 >> 5;
    int tid = threadIdx.x;

    {
        int j = tid >> 5, cc = tid & 31;
        ws[0][tid] = Wa_i[(c0+j)*32 + cc];
        ws[1][tid] = Wa_f[(c0+j)*32 + cc];
        ws[2][tid] = Wa_g[(c0+j)*32 + cc];
        ws[3][tid] = Wa_o[(c0+j)*32 + cc];
    }
    if (tid < 8) {
        bs[0][tid] = b_i[c0+tid]; bs[1][tid] = b_f[c0+tid];
        bs[2][tid] = b_g[c0+tid]; bs[3][tid] = b_o[c0+tid];
    }
    __syncthreads();

    int p = p0 + tid;
    const float* ab = g_a + ((size_t)(n*CCH) + g*32)*HWQ + p;

    float acc[4][8];
#pragma unroll
    for (int e = 0; e < 4; ++e)
#pragma unroll
        for (int j = 0; j < 8; ++j) acc[e][j] = 0.f;

#pragma unroll 4
    for (int cc = 0; cc < 32; ++cc) {
        float v = ab[cc*HWQ];
#pragma unroll
        for (int e = 0; e < 4; ++e)
#pragma unroll
            for (int j = 0; j < 8; ++j)
                acc[e][j] = fmaf(ws[e][j*32+cc], v, acc[e][j]);
    }

#pragma unroll
    for (int j = 0; j < 8; ++j) {
        int c = c0 + j;
        size_t off = ((size_t)(n*CCH) + c)*HWQ + p;
        float gi = sigm (acc[0][j] + g_gp[0][off] + bs[0][j]);
        float gf = sigm (acc[1][j] + g_gp[1][off] + bs[1][j]);
        float gg = ftanh(acc[2][j] + g_gp[2][off] + bs[2][j]);
        float go = sigm (acc[3][j] + g_gp[3][off] + bs[3][j]);
        float cn = gf * c_prev[off] + gi * gg;
        out[off] = go * ftanh(cn);
    }
}

// ---------------- launch ----------------------------------------------------
extern "C" void kernel_launch(void* const* d_in, const int* in_sizes, int n_in,
                              void* d_out, int out_size)
{
    (void)in_sizes; (void)n_in; (void)out_size;
    const float* inp    = (const float*)d_in[0];
    const float* h_prev = (const float*)d_in[1];
    const float* c_prev = (const float*)d_in[2];
    const float* Wx     = (const float*)d_in[3];
    const float* Wxg    = (const float*)d_in[4];
    const float* tau    = (const float*)d_in[5];
    const float* Wq     = (const float*)d_in[6];
    const float* Wk     = (const float*)d_in[7];
    const float* Wv     = (const float*)d_in[8];
    const float* Wa_i   = (const float*)d_in[9];
    const float* Wxh_i  = (const float*)d_in[10];
    const float* b_i    = (const float*)d_in[11];
    const float* Wa_f   = (const float*)d_in[12];
    const float* Wxh_f  = (const float*)d_in[13];
    const float* b_f    = (const float*)d_in[14];
    const float* Wa_g   = (const float*)d_in[15];
    const float* Wxh_g  = (const float*)d_in[16];
    const float* b_g    = (const float*)d_in[17];
    const float* Wa_o   = (const float*)d_in[18];
    const float* Wxh_o  = (const float*)d_in[19];
    const float* b_o    = (const float*)d_in[20];
    float* out = (float*)d_out;

    const int SMEM_S = (ITSZ + 2*160*36) * 4;   // 202752
    const int SMEM_V = (ITSZ + 2*64*36)  * 4;   // 175104

    cudaFuncSetAttribute(attn_kernel,
                         cudaFuncAttributeMaxDynamicSharedMemorySize, ATTN_SMEM);
    cudaFuncSetAttribute(conv_mma_kernel<160,0,48,10>,
                         cudaFuncAttributeMaxDynamicSharedMemorySize, SMEM_S);
    cudaFuncSetAttribute(conv_mma_kernel<64,4,40,4>,
                         cudaFuncAttributeMaxDynamicSharedMemorySize, SMEM_V);

    zero_xh2_kernel<<<2048, 256>>>();
    wtrans_kernel<<<4096, 256>>>(Wq, Wxh_i, Wxh_f, Wxh_g, Wxh_o, Wk, Wv);
    proj_kernel<<<dim3(9, 32, 4), 256>>>(inp, h_prev, Wx, Wxg);
    conv_mma_kernel<160,0,48,10><<<dim3(9, 8, 4), 256, SMEM_S>>>();
    conv_mma_kernel<64,4,40,4><<<dim3(9, 8, 4), 256, SMEM_V>>>();
    attn_kernel<<<NN*GG*144, 256, ATTN_SMEM>>>(tau);
    gates_kernel<<<dim3(9, 32, 4), 256>>>(Wa_i, Wa_f, Wa_g, Wa_o,
                                          b_i, b_f, b_g, b_o, c_prev, out);
}

// round 5
// speedup vs baseline: 3.6733x; 1.3780x over previous
#include <cuda_runtime.h>
#include <cstdint>
#include <math.h>

// Problem constants
#define NN   4
#define II   64
#define CCH  256
#define GG   8
#define CG   32
#define KS   9
#define HH   48
#define HWQ  (48*48)   // 2304
#define HD   40
#define DD   (40*40)   // 1600
#define PW   56        // padded width/height (48 + 2*4)
#define PHW  (56*56)   // 3136

// ---------------- scratch (device globals; no allocation allowed) -----------
__device__ __align__(128) float g_xh2[NN*GG*PHW*64];  // padded channel-last xh
__device__ __align__(128) float g_wS[GG*81*160*64];   // [g][tap][row(5conv*32)][ci]
__device__ __align__(128) float g_wV[GG*81*64*64];    // [g][tap][row(2conv*32)][ci]
__device__ __align__(128) float g_q [NN*CCH*HWQ];
__device__ __align__(128) float g_k [NN*CCH*DD];
__device__ __align__(128) float g_v [NN*CCH*DD];
__device__ __align__(128) float g_a [NN*CCH*HWQ];
__device__ __align__(128) float g_gp[4][NN*CCH*HWQ];

__device__ __forceinline__ float to_tf32(float x) {
    float r; asm("cvt.rna.tf32.f32 %0, %1;" : "=f"(r) : "f"(x)); return r;
}
// FFMA-only exp for x <= 0 (softmax): e^x = 2^(x*log2e), magic-number split.
__device__ __forceinline__ float fastexp(float x) {
    float z = fmaxf(x * 1.4426950408889634f, -120.f);
    float t = z + 12582912.f;                    // round-to-int in mantissa
    int   e = __float_as_int(t) - 0x4B400000;    // integer part (signed)
    float f = z - (t - 12582912.f);              // frac in [-0.5, 0.5]
    float p = fmaf(f, 0.0013333558f, 0.0096181291f);
    p = fmaf(f, p, 0.0555041087f);
    p = fmaf(f, p, 0.2402265069f);
    p = fmaf(f, p, 0.69314718056f);
    p = fmaf(f, p, 1.0f);
    return __int_as_float(__float_as_int(p) + (e << 23));
}
__device__ __forceinline__ float ftanh(float x) {
    float t; asm("tanh.approx.f32 %0, %1;" : "=f"(t) : "f"(x)); return t;
}
__device__ __forceinline__ float sigm(float x) {
    return fmaf(ftanh(x * 0.5f), 0.5f, 0.5f);
}

// m16n8k8 tf32 mma.sync
__device__ __forceinline__ void mma8(float* c, const uint32_t* a,
                                     uint32_t b0, uint32_t b1) {
    asm volatile(
        "mma.sync.aligned.m16n8k8.row.col.f32.tf32.tf32.f32 "
        "{%0,%1,%2,%3}, {%4,%5,%6,%7}, {%8,%9}, {%0,%1,%2,%3};"
        : "+f"(c[0]), "+f"(c[1]), "+f"(c[2]), "+f"(c[3])
        : "r"(a[0]), "r"(a[1]), "r"(a[2]), "r"(a[3]), "r"(b0), "r"(b1));
}
__device__ __forceinline__ void cp16(uint32_t dst, const void* src) {
    asm volatile("cp.async.cg.shared.global [%0], [%1], 16;" :: "r"(dst), "l"(src));
}
__device__ __forceinline__ uint32_t smem_u32(const void* p) {
    uint32_t a;
    asm("{ .reg .u64 t; cvta.to.shared.u64 t, %1; cvt.u32.u64 %0, t; }" : "=r"(a) : "l"(p));
    return a;
}

// ---------------- 0: zero padded xh buffer ----------------------------------
__global__ void zero_xh2_kernel() {
    size_t total4 = (size_t)NN*GG*PHW*64/4;
    float4* p = reinterpret_cast<float4*>(g_xh2);
    for (size_t i = (size_t)blockIdx.x*blockDim.x + threadIdx.x; i < total4;
         i += (size_t)gridDim.x*blockDim.x)
        p[i] = make_float4(0.f,0.f,0.f,0.f);
}

// ---------------- 0b: weight transpose (+ tf32 rna pre-round) ---------------
__global__ void wtrans_kernel(const float* __restrict__ Wq, const float* __restrict__ Wi,
                              const float* __restrict__ Wf, const float* __restrict__ Wg,
                              const float* __restrict__ Wo, const float* __restrict__ Wk,
                              const float* __restrict__ Wv)
{
    const int total_s = GG*81*160*64;
    const int total_v = GG*81*64*64;
    for (int o = blockIdx.x*blockDim.x + threadIdx.x; o < total_s + total_v;
         o += gridDim.x*blockDim.x) {
        if (o < total_s) {
            int ci = o & 63;
            int r  = (o >> 6) % 160;
            int k  = ((o >> 6) / 160) % 81;
            int g  = o / (64*160*81);
            int j = r >> 5, co = r & 31;
            const float* W = (j==0)?Wq:(j==1)?Wi:(j==2)?Wf:(j==3)?Wg:Wo;
            g_wS[o] = to_tf32(W[((size_t)(g*32+co)*64 + ci)*81 + k]);
        } else {
            int o2 = o - total_s;
            int ci = o2 & 63;
            int r  = (o2 >> 6) & 63;
            int k  = ((o2 >> 6) >> 6) % 81;
            int g  = o2 / (64*64*81);
            const float* W = (r < 32) ? Wk : Wv;
            g_wV[o2] = to_tf32(W[((size_t)(g*32+(r&31))*64 + ci)*81 + k]);
        }
    }
}

// ---------------- 1: projection + build padded channel-last xh --------------
__global__ __launch_bounds__(256)
void proj_kernel(const float* __restrict__ inp, const float* __restrict__ h,
                 const float* __restrict__ Wx, const float* __restrict__ Wxg)
{
    __shared__ float ws[8*320];
    int n  = blockIdx.z;
    int c0 = blockIdx.y * 8;
    int p0 = blockIdx.x * 256;
    int tid = threadIdx.x;

    for (int idx = tid; idx < 8*320; idx += 256) {
        int j = idx / 320, ic = idx - j*320;
        ws[idx] = (ic < 64) ? Wx[(c0+j)*64 + ic] : Wxg[(c0+j)*256 + (ic-64)];
    }
    __syncthreads();

    int p = p0 + tid;
    float acc[8];
#pragma unroll
    for (int j = 0; j < 8; ++j) acc[j] = 0.f;

    const float* ib = inp + (size_t)n*II*HWQ + p;
    const float* hb = h   + (size_t)n*CCH*HWQ + p;

#pragma unroll 4
    for (int ic = 0; ic < 64; ++ic) {
        float v = ib[ic*HWQ];
#pragma unroll
        for (int j = 0; j < 8; ++j) acc[j] = fmaf(ws[j*320+ic], v, acc[j]);
    }
#pragma unroll 4
    for (int ic = 0; ic < 256; ++ic) {
        float v = hb[ic*HWQ];
#pragma unroll
        for (int j = 0; j < 8; ++j) acc[j] = fmaf(ws[j*320+64+ic], v, acc[j]);
    }

    int y = p / 48, x = p - y*48;
    int g = c0 >> 5;
    float* xb = g_xh2 + ((size_t)(n*GG + g)*PHW + (y+4)*PW + (x+4))*64;
#pragma unroll
    for (int j = 0; j < 8; ++j) {
        int cg = (c0 + j) & 31;
        xb[cg]      = to_tf32(acc[j]);
        xb[32 + cg] = to_tf32(hb[(c0+j)*HWQ]);
    }
}

// ---------------- 2: grouped KxK conv via mma.sync tf32 ---------------------
#define ITSZ (24*24*68)     // 39168 floats
template<int NC, int BASE, int OW, int TN>
__global__ __launch_bounds__(256, 1)
void conv_mma_kernel()
{
    extern __shared__ float smf[];
    float* IT = smf;

    const int tid = threadIdx.x;
    const int wid = tid >> 5, lane = tid & 31;
    const int gid = lane >> 2, tig = lane & 3;
    const int my0 = (wid >> 1) * 4;
    const int nb  = (wid & 1) * (NC/2);

    const int g  = blockIdx.y;
    const int n  = blockIdx.z;
    const int x0 = (blockIdx.x % 3) * 16;
    const int y0 = (blockIdx.x / 3) * 16;

    float* outs[5];
    if (NC == 160) { outs[0]=g_q; outs[1]=g_gp[0]; outs[2]=g_gp[1]; outs[3]=g_gp[2]; outs[4]=g_gp[3]; }
    else           { outs[0]=g_k; outs[1]=g_v; outs[2]=nullptr; outs[3]=nullptr; outs[4]=nullptr; }

    const float* xsrc = g_xh2 + (size_t)(n*GG + g)*PHW*64;
    const float* wg   = ((NC == 160) ? g_wS : g_wV) + (size_t)g*81*NC*64;
    const uint32_t smemB = smem_u32(smf) + ITSZ*4;

    auto stageB = [&](int t, int buf) {
        int kk = t >> 1, ci0 = (t & 1) * 32;
        const float* wsrc = wg + (size_t)kk*NC*64 + ci0;
        uint32_t bbase = smemB + (uint32_t)buf*(NC*36*4);
        for (int u = tid; u < NC*8; u += 256) {
            int n2 = u >> 3, seg = u & 7;
            cp16(bbase + (uint32_t)(n2*36 + seg*4)*4, wsrc + n2*64 + seg*4);
        }
    };

    stageB(0, 0);
    asm volatile("cp.async.commit_group;" ::: "memory");
    for (int u = tid; u < 24*24*16; u += 256) {
        int f4 = u & 15, pos = u >> 4;
        int yy = pos / 24, xx = pos - yy*24;
        int gy = min(y0 + BASE + yy, 55), gx = min(x0 + BASE + xx, 55);
        float4 v = *reinterpret_cast<const float4*>(xsrc + (size_t)(gy*PW + gx)*64 + f4*4);
        *reinterpret_cast<float4*>(IT + (yy*24 + xx)*68 + f4*4) = v;
    }

    float acc[4][TN][4];
#pragma unroll
    for (int mi = 0; mi < 4; ++mi)
#pragma unroll
        for (int nj = 0; nj < TN; ++nj)
#pragma unroll
            for (int r = 0; r < 4; ++r) acc[mi][nj][r] = 0.f;

    asm volatile("cp.async.wait_group 0;" ::: "memory");
    __syncthreads();

    for (int t = 0; t < 162; ++t) {
        if (t + 1 < 162) {
            stageB(t+1, (t+1) & 1);
            asm volatile("cp.async.commit_group;" ::: "memory");
            asm volatile("cp.async.wait_group 1;" ::: "memory");
        } else {
            asm volatile("cp.async.wait_group 0;" ::: "memory");
        }
        __syncthreads();

        const int kk = t >> 1, ci0 = (t & 1) * 32;
        const int ky = kk / 9, kx = kk - ky*9;
        const float* Bsp = smf + ITSZ + (t & 1)*(NC*36);

#pragma unroll
        for (int ks = 0; ks < 4; ++ks) {
            const int kb = ks*8 + tig;
            uint32_t a[4][4];
#pragma unroll
            for (int mi = 0; mi < 4; ++mi) {
                const float* p = IT + ((my0 + mi + ky)*24 + kx + gid)*68 + ci0 + kb;
                a[mi][0] = __float_as_uint(p[0]);
                a[mi][1] = __float_as_uint(p[544]);
                a[mi][2] = __float_as_uint(p[4]);
                a[mi][3] = __float_as_uint(p[548]);
            }
#pragma unroll
            for (int nj = 0; nj < TN; ++nj) {
                const float* bp = Bsp + (nb + nj*8 + gid)*36 + kb;
                uint32_t b0 = __float_as_uint(bp[0]);
                uint32_t b1 = __float_as_uint(bp[4]);
#pragma unroll
                for (int mi = 0; mi < 4; ++mi)
                    mma8(acc[mi][nj], a[mi], b0, b1);
            }
        }
        __syncthreads();
    }

#pragma unroll
    for (int mi = 0; mi < 4; ++mi) {
        int y = y0 + my0 + mi;
        if (y >= OW) continue;
#pragma unroll
        for (int nj = 0; nj < TN; ++nj)
#pragma unroll
            for (int r = 0; r < 4; ++r) {
                int x = x0 + gid + ((r >> 1) << 3);
                if (x < OW) {
                    int nc = nb + nj*8 + tig*2 + (r & 1);
                    int conv = nc >> 5, cg = nc & 31;
                    outs[conv][((size_t)(n*CCH + g*32 + cg)*OW + y)*OW + x] = acc[mi][nj][r];
                }
            }
    }
}

// ---------------- 3: attention via mma.sync per (n, g, 16-query tile) -------
// Phase1: S[16 q][1600 d] = tau * Q^T K  (mma, K-dim = 32 channels)
// Phase2: O[16 q][32 c]   = P V^T        (mma, K-dim = 1600 d, warp-split)
#define LSP  1604            // logits row stride (bank-safe)
#define CHW  320             // staged K/V chunk width
#define CHP  324             // chunk row stride
#define ATTN_SMEM ((16*LSP + 16*36 + 32*CHP + 8*16*33) * 4)

__global__ __launch_bounds__(256)
void attn_kernel(const float* __restrict__ tau)
{
    extern __shared__ float smf[];
    float* ls = smf;                  // [16][LSP]
    float* qs = ls + 16*LSP;          // [16][36]
    float* kv = qs + 16*36;           // [32][CHP]
    float* os = kv + 32*CHP;          // [8][16][33] phase-2 partials

    int bz = blockIdx.x;
    int qt = bz % 144;
    int g  = (bz / 144) & 7;
    int n  = bz / 1152;
    int q0 = qt * 16;

    const float* qb = g_q + ((size_t)(n*CCH) + g*32)*HWQ + q0;
    const float* kb = g_k + ((size_t)(n*CCH) + g*32)*DD;
    const float* vb = g_v + ((size_t)(n*CCH) + g*32)*DD;
    int tid = threadIdx.x;
    int wid = tid >> 5, lane = tid & 31;
    int gid = lane >> 2, tig = lane & 3;
    uint32_t kvb = smem_u32(kv);

    // load Q [16 q][32 c] -> qs[q][c], stride 36 (conflict-free frags)
    for (int idx = tid; idx < 512; idx += 256) {
        int qi = idx >> 5, c = idx & 31;
        qs[qi*36 + c] = qb[c*HWQ + qi];
    }
    float tg = tau[g];

    // ---- phase 1: logits ----
    for (int ch = 0; ch < 5; ++ch) {
        int d0 = ch*CHW;
        __syncthreads();                     // kv reuse guard
        for (int u = tid; u < 32*80; u += 256) {
            int c = u >> 6 << 1 | 0; // placeholder (recomputed below)
            int cc = u / 80, seg = u - cc*80;
            cp16(kvb + (uint32_t)(cc*CHP + seg*4)*4, kb + (size_t)cc*DD + d0 + seg*4);
            (void)c;
        }
        asm volatile("cp.async.commit_group;" ::: "memory");
        asm volatile("cp.async.wait_group 0;" ::: "memory");
        __syncthreads();

        int nw = wid*40;                     // warp's 40-col slice of this chunk
        float acc[5][4];
#pragma unroll
        for (int nj = 0; nj < 5; ++nj)
#pragma unroll
            for (int r = 0; r < 4; ++r) acc[nj][r] = 0.f;

#pragma unroll
        for (int ks = 0; ks < 4; ++ks) {
            int kbi = ks*8;
            uint32_t a[4];
            a[0] = __float_as_uint(qs[gid*36     + kbi + tig]);
            a[1] = __float_as_uint(qs[(gid+8)*36 + kbi + tig]);
            a[2] = __float_as_uint(qs[gid*36     + kbi + tig + 4]);
            a[3] = __float_as_uint(qs[(gid+8)*36 + kbi + tig + 4]);
#pragma unroll
            for (int nj = 0; nj < 5; ++nj) {
                uint32_t b0 = __float_as_uint(kv[(kbi+tig)*CHP   + nw + nj*8 + gid]);
                uint32_t b1 = __float_as_uint(kv[(kbi+tig+4)*CHP + nw + nj*8 + gid]);
                mma8(acc[nj], a, b0, b1);
            }
        }
#pragma unroll
        for (int nj = 0; nj < 5; ++nj) {
            int d = d0 + nw + nj*8 + 2*tig;
            float2 lo = make_float2(acc[nj][0]*tg, acc[nj][1]*tg);
            float2 hi = make_float2(acc[nj][2]*tg, acc[nj][3]*tg);
            *reinterpret_cast<float2*>(ls + gid*LSP     + d) = lo;
            *reinterpret_cast<float2*>(ls + (gid+8)*LSP + d) = hi;
        }
    }
    __syncthreads();

    // ---- softmax (FFMA exp), one warp per row ----
    for (int q = wid; q < 16; q += 8) {
        float* row = ls + q*LSP;
        float m = -1e30f;
        for (int d = lane; d < DD; d += 32) m = fmaxf(m, row[d]);
#pragma unroll
        for (int off = 16; off; off >>= 1) m = fmaxf(m, __shfl_xor_sync(~0u, m, off));
        float s = 0.f;
        for (int d = lane; d < DD; d += 32) { float e = fastexp(row[d]-m); row[d] = e; s += e; }
#pragma unroll
        for (int off = 16; off; off >>= 1) s += __shfl_xor_sync(~0u, s, off);
        float inv = 1.f / s;
        for (int d = lane; d < DD; d += 32) row[d] *= inv;
    }

    // ---- phase 2: O = P V^T (K-dim split across warps) ----
    float acc2[4][4];
#pragma unroll
    for (int nj = 0; nj < 4; ++nj)
#pragma unroll
        for (int r = 0; r < 4; ++r) acc2[nj][r] = 0.f;

    for (int ch = 0; ch < 5; ++ch) {
        int d0 = ch*CHW;
        __syncthreads();
        for (int u = tid; u < 32*80; u += 256) {
            int cc = u / 80, seg = u - cc*80;
            cp16(kvb + (uint32_t)(cc*CHP + seg*4)*4, vb + (size_t)cc*DD + d0 + seg*4);
        }
        asm volatile("cp.async.commit_group;" ::: "memory");
        asm volatile("cp.async.wait_group 0;" ::: "memory");
        __syncthreads();

#pragma unroll
        for (int ks = 0; ks < 5; ++ks) {
            int kl = wid*40 + ks*8;          // d-offset within chunk
            uint32_t a[4];
            a[0] = __float_as_uint(ls[gid*LSP     + d0 + kl + tig]);
            a[1] = __float_as_uint(ls[(gid+8)*LSP + d0 + kl + tig]);
            a[2] = __float_as_uint(ls[gid*LSP     + d0 + kl + tig + 4]);
            a[3] = __float_as_uint(ls[(gid+8)*LSP + d0 + kl + tig + 4]);
#pragma unroll
            for (int nj = 0; nj < 4; ++nj) {
                uint32_t b0 = __float_as_uint(kv[(nj*8+gid)*CHP + kl + tig]);
                uint32_t b1 = __float_as_uint(kv[(nj*8+gid)*CHP + kl + tig + 4]);
                mma8(acc2[nj], a, b0, b1);
            }
        }
    }

    // partial stores + cross-warp reduce
#pragma unroll
    for (int nj = 0; nj < 4; ++nj)
#pragma unroll
        for (int r = 0; r < 4; ++r) {
            int q = gid + ((r >> 1) << 3);
            int c = nj*8 + tig*2 + (r & 1);
            os[(wid*16 + q)*33 + c] = acc2[nj][r];
        }
    __syncthreads();

    for (int idx = tid; idx < 512; idx += 256) {
        int q = idx >> 5, c = idx & 31;
        float s = 0.f;
#pragma unroll
        for (int w = 0; w < 8; ++w) s += os[(w*16 + q)*33 + c];
        g_a[((size_t)(n*CCH) + g*32 + c)*HWQ + q0 + q] = s;
    }
}

// ---------------- 4: gates (grouped 1x1 on a) + cell update -----------------
__global__ __launch_bounds__(256)
void gates_kernel(const float* __restrict__ Wa_i, const float* __restrict__ Wa_f,
                  const float* __restrict__ Wa_g, const float* __restrict__ Wa_o,
                  const float* __restrict__ b_i,  const float* __restrict__ b_f,
                  const float* __restrict__ b_g,  const float* __restrict__ b_o,
                  const float* __restrict__ c_prev, float* __restrict__ out)
{
    __shared__ float ws[4][8*32];
    __shared__ float bs[4][8];
    int n  = blockIdx.z;
    int c0 = blockIdx.y * 8;
    int p0 = blockIdx.x * 256;
    int g  = c0 >> 5;
    int tid = threadIdx.x;

    {
        int j = tid >> 5, cc = tid & 31;
        ws[0][tid] = Wa_i[(c0+j)*32 + cc];
        ws[1][tid] = Wa_f[(c0+j)*32 + cc];
        ws[2][tid] = Wa_g[(c0+j)*32 + cc];
        ws[3][tid] = Wa_o[(c0+j)*32 + cc];
    }
    if (tid < 8) {
        bs[0][tid] = b_i[c0+tid]; bs[1][tid] = b_f[c0+tid];
        bs[2][tid] = b_g[c0+tid]; bs[3][tid] = b_o[c0+tid];
    }
    __syncthreads();

    int p = p0 + tid;
    const float* ab = g_a + ((size_t)(n*CCH) + g*32)*HWQ + p;

    float acc[4][8];
#pragma unroll
    for (int e = 0; e < 4; ++e)
#pragma unroll
        for (int j = 0; j < 8; ++j) acc[e][j] = 0.f;

#pragma unroll 4
    for (int cc = 0; cc < 32; ++cc) {
        float v = ab[cc*HWQ];
#pragma unroll
        for (int e = 0; e < 4; ++e)
#pragma unroll
            for (int j = 0; j < 8; ++j)
                acc[e][j] = fmaf(ws[e][j*32+cc], v, acc[e][j]);
    }

#pragma unroll
    for (int j = 0; j < 8; ++j) {
        int c = c0 + j;
        size_t off = ((size_t)(n*CCH) + c)*HWQ + p;
        float gi = sigm (acc[0][j] + g_gp[0][off] + bs[0][j]);
        float gf = sigm (acc[1][j] + g_gp[1][off] + bs[1][j]);
        float gg = ftanh(acc[2][j] + g_gp[2][off] + bs[2][j]);
        float go = sigm (acc[3][j] + g_gp[3][off] + bs[3][j]);
        float cn = gf * c_prev[off] + gi * gg;
        out[off] = go * ftanh(cn);
    }
}

// ---------------- launch ----------------------------------------------------
extern "C" void kernel_launch(void* const* d_in, const int* in_sizes, int n_in,
                              void* d_out, int out_size)
{
    (void)in_sizes; (void)n_in; (void)out_size;
    const float* inp    = (const float*)d_in[0];
    const float* h_prev = (const float*)d_in[1];
    const float* c_prev = (const float*)d_in[2];
    const float* Wx     = (const float*)d_in[3];
    const float* Wxg    = (const float*)d_in[4];
    const float* tau    = (const float*)d_in[5];
    const float* Wq     = (const float*)d_in[6];
    const float* Wk     = (const float*)d_in[7];
    const float* Wv     = (const float*)d_in[8];
    const float* Wa_i   = (const float*)d_in[9];
    const float* Wxh_i  = (const float*)d_in[10];
    const float* b_i    = (const float*)d_in[11];
    const float* Wa_f   = (const float*)d_in[12];
    const float* Wxh_f  = (const float*)d_in[13];
    const float* b_f    = (const float*)d_in[14];
    const float* Wa_g   = (const float*)d_in[15];
    const float* Wxh_g  = (const float*)d_in[16];
    const float* b_g    = (const float*)d_in[17];
    const float* Wa_o   = (const float*)d_in[18];
    const float* Wxh_o  = (const float*)d_in[19];
    const float* b_o    = (const float*)d_in[20];
    float* out = (float*)d_out;

    const int SMEM_S = (ITSZ + 2*160*36) * 4;   // 202752
    const int SMEM_V = (ITSZ + 2*64*36)  * 4;   // 175104

    cudaFuncSetAttribute(attn_kernel,
                         cudaFuncAttributeMaxDynamicSharedMemorySize, ATTN_SMEM);
    cudaFuncSetAttribute(conv_mma_kernel<160,0,48,10>,
                         cudaFuncAttributeMaxDynamicSharedMemorySize, SMEM_S);
    cudaFuncSetAttribute(conv_mma_kernel<64,4,40,4>,
                         cudaFuncAttributeMaxDynamicSharedMemorySize, SMEM_V);

    zero_xh2_kernel<<<2048, 256>>>();
    wtrans_kernel<<<4096, 256>>>(Wq, Wxh_i, Wxh_f, Wxh_g, Wxh_o, Wk, Wv);
    proj_kernel<<<dim3(9, 32, 4), 256>>>(inp, h_prev, Wx, Wxg);
    conv_mma_kernel<160,0,48,10><<<dim3(9, 8, 4), 256, SMEM_S>>>();
    conv_mma_kernel<64,4,40,4><<<dim3(9, 8, 4), 256, SMEM_V>>>();
    attn_kernel<<<NN*GG*144, 256, ATTN_SMEM>>>(tau);
    gates_kernel<<<dim3(9, 32, 4), 256>>>(Wa_i, Wa_f, Wa_g, Wa_o,
                                          b_i, b_f, b_g, b_o, c_prev, out);
}

// round 6
// speedup vs baseline: 3.7721x; 1.0269x over previous
#include <cuda_runtime.h>
#include <cstdint>
#include <math.h>

// Problem constants
#define NN   4
#define II   64
#define CCH  256
#define GG   8
#define CG   32
#define KS   9
#define HH   48
#define HWQ  (48*48)   // 2304
#define HD   40
#define DD   (40*40)   // 1600
#define PW   56        // padded width/height (48 + 2*4)
#define PHW  (56*56)   // 3136

// ---------------- scratch (device globals; no allocation allowed) -----------
__device__ __align__(128) float g_xh2[NN*GG*PHW*64];  // padded channel-last xh
__device__ __align__(128) float g_wS[GG*81*160*64];   // [g][tap][row(5conv*32)][ci]
__device__ __align__(128) float g_wV[GG*81*64*64];    // [g][tap][row(2conv*32)][ci]
__device__ __align__(128) float g_q [NN*CCH*HWQ];
__device__ __align__(128) float g_k [NN*CCH*DD];
__device__ __align__(128) float g_v [NN*CCH*DD];
__device__ __align__(128) float g_gp[4][NN*CCH*HWQ];

__device__ __forceinline__ float to_tf32(float x) {
    float r; asm("cvt.rna.tf32.f32 %0, %1;" : "=f"(r) : "f"(x)); return r;
}
// FFMA-only exp for softmax
__device__ __forceinline__ float fastexp(float x) {
    float z = fmaxf(x * 1.4426950408889634f, -120.f);
    float t = z + 12582912.f;
    int   e = __float_as_int(t) - 0x4B400000;
    float f = z - (t - 12582912.f);
    float p = fmaf(f, 0.0013333558f, 0.0096181291f);
    p = fmaf(f, p, 0.0555041087f);
    p = fmaf(f, p, 0.2402265069f);
    p = fmaf(f, p, 0.69314718056f);
    p = fmaf(f, p, 1.0f);
    return __int_as_float(__float_as_int(p) + (e << 23));
}
__device__ __forceinline__ float ftanh(float x) {
    float t; asm("tanh.approx.f32 %0, %1;" : "=f"(t) : "f"(x)); return t;
}
__device__ __forceinline__ float sigm(float x) {
    return fmaf(ftanh(x * 0.5f), 0.5f, 0.5f);
}

// m16n8k8 tf32 mma.sync
__device__ __forceinline__ void mma8(float* c, const uint32_t* a,
                                     uint32_t b0, uint32_t b1) {
    asm volatile(
        "mma.sync.aligned.m16n8k8.row.col.f32.tf32.tf32.f32 "
        "{%0,%1,%2,%3}, {%4,%5,%6,%7}, {%8,%9}, {%0,%1,%2,%3};"
        : "+f"(c[0]), "+f"(c[1]), "+f"(c[2]), "+f"(c[3])
        : "r"(a[0]), "r"(a[1]), "r"(a[2]), "r"(a[3]), "r"(b0), "r"(b1));
}
__device__ __forceinline__ void cp16(uint32_t dst, const void* src) {
    asm volatile("cp.async.cg.shared.global [%0], [%1], 16;" :: "r"(dst), "l"(src));
}
__device__ __forceinline__ uint32_t smem_u32(const void* p) {
    uint32_t a;
    asm("{ .reg .u64 t; cvta.to.shared.u64 t, %1; cvt.u32.u64 %0, t; }" : "=r"(a) : "l"(p));
    return a;
}

// ---------------- 0: zero padded xh buffer ----------------------------------
__global__ void zero_xh2_kernel() {
    size_t total4 = (size_t)NN*GG*PHW*64/4;
    float4* p = reinterpret_cast<float4*>(g_xh2);
    for (size_t i = (size_t)blockIdx.x*blockDim.x + threadIdx.x; i < total4;
         i += (size_t)gridDim.x*blockDim.x)
        p[i] = make_float4(0.f,0.f,0.f,0.f);
}

// ---------------- 0b: weight transpose via smem tile (coalesced) ------------
// One block per (g, output row). Loads contiguous [64ci][81k] panel, writes
// [k][row][ci]. smem bank stride 81 = 17 mod 32 -> conflict-free transpose.
__global__ __launch_bounds__(256)
void wtrans_kernel(const float* __restrict__ Wq, const float* __restrict__ Wi,
                   const float* __restrict__ Wf, const float* __restrict__ Wg,
                   const float* __restrict__ Wo, const float* __restrict__ Wk,
                   const float* __restrict__ Wv)
{
    __shared__ float sm[5184];
    int b = blockIdx.x;          // 0..1791
    int g = b / 224;
    int r = b % 224;
    int tid = threadIdx.x;

    const float* W;
    float* dst;
    int row, NCr, rr;
    if (r < 160) {
        int j = r >> 5;
        W = (j==0)?Wq:(j==1)?Wi:(j==2)?Wf:(j==3)?Wg:Wo;
        row = r & 31; dst = g_wS; NCr = 160; rr = r;
    } else {
        int r2 = r - 160;
        W = (r2 < 32) ? Wk : Wv;
        row = r2 & 31; dst = g_wV; NCr = 64; rr = r2;
    }
    const float* src = W + (size_t)(g*32 + row)*5184;
    for (int u = tid; u < 5184; u += 256) sm[u] = src[u];
    __syncthreads();
    for (int u = tid; u < 5184; u += 256) {
        int k = u >> 6, ci = u & 63;
        dst[((size_t)(g*81 + k)*NCr + rr)*64 + ci] = to_tf32(sm[ci*81 + k]);
    }
}

// ---------------- 1: projection + build padded channel-last xh --------------
__global__ __launch_bounds__(256)
void proj_kernel(const float* __restrict__ inp, const float* __restrict__ h,
                 const float* __restrict__ Wx, const float* __restrict__ Wxg)
{
    __shared__ float ws[8*320];
    int n  = blockIdx.z;
    int c0 = blockIdx.y * 8;
    int p0 = blockIdx.x * 256;
    int tid = threadIdx.x;

    for (int idx = tid; idx < 8*320; idx += 256) {
        int j = idx / 320, ic = idx - j*320;
        ws[idx] = (ic < 64) ? Wx[(c0+j)*64 + ic] : Wxg[(c0+j)*256 + (ic-64)];
    }
    __syncthreads();

    int p = p0 + tid;
    float acc[8];
#pragma unroll
    for (int j = 0; j < 8; ++j) acc[j] = 0.f;

    const float* ib = inp + (size_t)n*II*HWQ + p;
    const float* hb = h   + (size_t)n*CCH*HWQ + p;

#pragma unroll 4
    for (int ic = 0; ic < 64; ++ic) {
        float v = ib[ic*HWQ];
#pragma unroll
        for (int j = 0; j < 8; ++j) acc[j] = fmaf(ws[j*320+ic], v, acc[j]);
    }
#pragma unroll 4
    for (int ic = 0; ic < 256; ++ic) {
        float v = hb[ic*HWQ];
#pragma unroll
        for (int j = 0; j < 8; ++j) acc[j] = fmaf(ws[j*320+64+ic], v, acc[j]);
    }

    int y = p / 48, x = p - y*48;
    int g = c0 >> 5;
    float* xb = g_xh2 + ((size_t)(n*GG + g)*PHW + (y+4)*PW + (x+4))*64;
#pragma unroll
    for (int j = 0; j < 8; ++j) {
        int cg = (c0 + j) & 31;
        xb[cg]      = to_tf32(acc[j]);
        xb[32 + cg] = to_tf32(hb[(c0+j)*HWQ]);
    }
}

// ---------------- 2: grouped KxK conv via mma.sync tf32 ---------------------
// Persistent IT tile; B chunks CK-ci wide, 3-deep cp.async pipeline,
// one __syncthreads per iteration (wait -> sync -> stage(t+2) -> mma).
#define ITSZ (24*24*68)     // 39168 floats
template<int NC, int BASE, int OW, int TN, int CK>
__global__ __launch_bounds__(256, 1)
void conv_mma_kernel()
{
    extern __shared__ float smf[];
    float* IT = smf;
    constexpr int BSTR = CK + 4;
    constexpr int T    = 81 * (64 / CK);
    constexpr int KSN  = CK / 8;

    const int tid = threadIdx.x;
    const int wid = tid >> 5, lane = tid & 31;
    const int gid = lane >> 2, tig = lane & 3;
    const int my0 = (wid >> 1) * 4;
    const int nb  = (wid & 1) * (NC/2);

    const int g  = blockIdx.y;
    const int n  = blockIdx.z;
    const int x0 = (blockIdx.x % 3) * 16;
    const int y0 = (blockIdx.x / 3) * 16;

    float* outs[5];
    if (NC == 160) { outs[0]=g_q; outs[1]=g_gp[0]; outs[2]=g_gp[1]; outs[3]=g_gp[2]; outs[4]=g_gp[3]; }
    else           { outs[0]=g_k; outs[1]=g_v; outs[2]=nullptr; outs[3]=nullptr; outs[4]=nullptr; }

    const float* xsrc = g_xh2 + (size_t)(n*GG + g)*PHW*64;
    const float* wg   = ((NC == 160) ? g_wS : g_wV) + (size_t)g*81*NC*64;
    const uint32_t smemB = smem_u32(smf) + ITSZ*4;

    auto stageB = [&](int t, int buf) {
        int kk  = (CK == 32) ? (t >> 1) : t;
        int ci0 = (CK == 32) ? ((t & 1) * 32) : 0;
        const float* wsrc = wg + (size_t)kk*NC*64 + ci0;
        uint32_t bbase = smemB + (uint32_t)buf*(NC*BSTR*4);
        for (int u = tid; u < NC*(CK/4); u += 256) {
            int n2 = u / (CK/4), seg = u % (CK/4);
            cp16(bbase + (uint32_t)(n2*BSTR + seg*4)*4, wsrc + n2*64 + seg*4);
        }
    };

    stageB(0, 0);
    asm volatile("cp.async.commit_group;" ::: "memory");
    stageB(1, 1);
    asm volatile("cp.async.commit_group;" ::: "memory");

    // persistent input tile
    for (int u = tid; u < 24*24*16; u += 256) {
        int f4 = u & 15, pos = u >> 4;
        int yy = pos / 24, xx = pos - yy*24;
        int gy = min(y0 + BASE + yy, 55), gx = min(x0 + BASE + xx, 55);
        float4 v = *reinterpret_cast<const float4*>(xsrc + (size_t)(gy*PW + gx)*64 + f4*4);
        *reinterpret_cast<float4*>(IT + (yy*24 + xx)*68 + f4*4) = v;
    }

    float acc[4][TN][4];
#pragma unroll
    for (int mi = 0; mi < 4; ++mi)
#pragma unroll
        for (int nj = 0; nj < TN; ++nj)
#pragma unroll
            for (int r = 0; r < 4; ++r) acc[mi][nj][r] = 0.f;

    for (int t = 0; t < T; ++t) {
        if (t == T-1) asm volatile("cp.async.wait_group 0;" ::: "memory");
        else          asm volatile("cp.async.wait_group 1;" ::: "memory");
        __syncthreads();
        if (t + 2 < T) {
            stageB(t+2, (t+2) % 3);
            asm volatile("cp.async.commit_group;" ::: "memory");
        }

        const int kk  = (CK == 32) ? (t >> 1) : t;
        const int ci0 = (CK == 32) ? ((t & 1) * 32) : 0;
        const int ky = kk / 9, kx = kk - ky*9;
        const float* Bsp = smf + ITSZ + (t % 3)*(NC*BSTR);

#pragma unroll
        for (int ks = 0; ks < KSN; ++ks) {
            const int kb = ks*8 + tig;
            uint32_t a[4][4];
#pragma unroll
            for (int mi = 0; mi < 4; ++mi) {
                const float* p = IT + ((my0 + mi + ky)*24 + kx + gid)*68 + ci0 + kb;
                a[mi][0] = __float_as_uint(p[0]);
                a[mi][1] = __float_as_uint(p[544]);
                a[mi][2] = __float_as_uint(p[4]);
                a[mi][3] = __float_as_uint(p[548]);
            }
#pragma unroll
            for (int nj = 0; nj < TN; ++nj) {
                const float* bp = Bsp + (nb + nj*8 + gid)*BSTR + kb;
                uint32_t b0 = __float_as_uint(bp[0]);
                uint32_t b1 = __float_as_uint(bp[4]);
#pragma unroll
                for (int mi = 0; mi < 4; ++mi)
                    mma8(acc[mi][nj], a[mi], b0, b1);
            }
        }
    }

#pragma unroll
    for (int mi = 0; mi < 4; ++mi) {
        int y = y0 + my0 + mi;
        if (y >= OW) continue;
#pragma unroll
        for (int nj = 0; nj < TN; ++nj)
#pragma unroll
            for (int r = 0; r < 4; ++r) {
                int x = x0 + gid + ((r >> 1) << 3);
                if (x < OW) {
                    int nc = nb + nj*8 + tig*2 + (r & 1);
                    int conv = nc >> 5, cg = nc & 31;
                    outs[conv][((size_t)(n*CCH + g*32 + cg)*OW + y)*OW + x] = acc[mi][nj][r];
                }
            }
    }
}

// ---------------- 3: attention (mma) + fused gates + cell update ------------
#define LSP  1604            // logits row stride
#define CHW  320             // staged K/V chunk width
#define CHP  324             // chunk row stride
#define ATTN_SMEM ((16*LSP + 16*36 + 32*CHP + 8*16*33) * 4)

__global__ __launch_bounds__(256)
void attn_kernel(const float* __restrict__ tau,
                 const float* __restrict__ Wa_i, const float* __restrict__ Wa_f,
                 const float* __restrict__ Wa_g, const float* __restrict__ Wa_o,
                 const float* __restrict__ b_i,  const float* __restrict__ b_f,
                 const float* __restrict__ b_g,  const float* __restrict__ b_o,
                 const float* __restrict__ c_prev, float* __restrict__ outp)
{
    extern __shared__ float smf[];
    float* ls = smf;                  // [16][LSP]
    float* qs = ls + 16*LSP;          // [16][36]   (reused as oq later)
    float* kv = qs + 16*36;           // [32][CHP]  (reused as gate weights)
    float* os = kv + 32*CHP;          // [8][16][33]

    int bz = blockIdx.x;
    int qt = bz % 144;
    int g  = (bz / 144) & 7;
    int n  = bz / 1152;
    int q0 = qt * 16;

    const float* qb = g_q + ((size_t)(n*CCH) + g*32)*HWQ + q0;
    const float* kb = g_k + ((size_t)(n*CCH) + g*32)*DD;
    const float* vb = g_v + ((size_t)(n*CCH) + g*32)*DD;
    int tid = threadIdx.x;
    int wid = tid >> 5, lane = tid & 31;
    int gid = lane >> 2, tig = lane & 3;
    uint32_t kvb = smem_u32(kv);

    for (int idx = tid; idx < 512; idx += 256) {
        int qi = idx >> 5, c = idx & 31;
        qs[qi*36 + c] = qb[c*HWQ + qi];
    }
    float tg = tau[g];

    // ---- phase 1: logits ----
    for (int ch = 0; ch < 5; ++ch) {
        int d0 = ch*CHW;
        __syncthreads();
        for (int u = tid; u < 32*80; u += 256) {
            int cc = u / 80, seg = u - cc*80;
            cp16(kvb + (uint32_t)(cc*CHP + seg*4)*4, kb + (size_t)cc*DD + d0 + seg*4);
        }
        asm volatile("cp.async.commit_group;" ::: "memory");
        asm volatile("cp.async.wait_group 0;" ::: "memory");
        __syncthreads();

        int nw = wid*40;
        float acc[5][4];
#pragma unroll
        for (int nj = 0; nj < 5; ++nj)
#pragma unroll
            for (int r = 0; r < 4; ++r) acc[nj][r] = 0.f;

#pragma unroll
        for (int ks = 0; ks < 4; ++ks) {
            int kbi = ks*8;
            uint32_t a[4];
            a[0] = __float_as_uint(qs[gid*36     + kbi + tig]);
            a[1] = __float_as_uint(qs[(gid+8)*36 + kbi + tig]);
            a[2] = __float_as_uint(qs[gid*36     + kbi + tig + 4]);
            a[3] = __float_as_uint(qs[(gid+8)*36 + kbi + tig + 4]);
#pragma unroll
            for (int nj = 0; nj < 5; ++nj) {
                uint32_t b0 = __float_as_uint(kv[(kbi+tig)*CHP   + nw + nj*8 + gid]);
                uint32_t b1 = __float_as_uint(kv[(kbi+tig+4)*CHP + nw + nj*8 + gid]);
                mma8(acc[nj], a, b0, b1);
            }
        }
#pragma unroll
        for (int nj = 0; nj < 5; ++nj) {
            int d = d0 + nw + nj*8 + 2*tig;
            float2 lo = make_float2(acc[nj][0]*tg, acc[nj][1]*tg);
            float2 hi = make_float2(acc[nj][2]*tg, acc[nj][3]*tg);
            *reinterpret_cast<float2*>(ls + gid*LSP     + d) = lo;
            *reinterpret_cast<float2*>(ls + (gid+8)*LSP + d) = hi;
        }
    }
    __syncthreads();

    // ---- softmax ----
    for (int q = wid; q < 16; q += 8) {
        float* row = ls + q*LSP;
        float m = -1e30f;
        for (int d = lane; d < DD; d += 32) m = fmaxf(m, row[d]);
#pragma unroll
        for (int off = 16; off; off >>= 1) m = fmaxf(m, __shfl_xor_sync(~0u, m, off));
        float s = 0.f;
        for (int d = lane; d < DD; d += 32) { float e = fastexp(row[d]-m); row[d] = e; s += e; }
#pragma unroll
        for (int off = 16; off; off >>= 1) s += __shfl_xor_sync(~0u, s, off);
        float inv = 1.f / s;
        for (int d = lane; d < DD; d += 32) row[d] *= inv;
    }

    // ---- phase 2: O = P V^T ----
    float acc2[4][4];
#pragma unroll
    for (int nj = 0; nj < 4; ++nj)
#pragma unroll
        for (int r = 0; r < 4; ++r) acc2[nj][r] = 0.f;

    for (int ch = 0; ch < 5; ++ch) {
        int d0 = ch*CHW;
        __syncthreads();
        for (int u = tid; u < 32*80; u += 256) {
            int cc = u / 80, seg = u - cc*80;
            cp16(kvb + (uint32_t)(cc*CHP + seg*4)*4, vb + (size_t)cc*DD + d0 + seg*4);
        }
        asm volatile("cp.async.commit_group;" ::: "memory");
        asm volatile("cp.async.wait_group 0;" ::: "memory");
        __syncthreads();

#pragma unroll
        for (int ks = 0; ks < 5; ++ks) {
            int kl = wid*40 + ks*8;
            uint32_t a[4];
            a[0] = __float_as_uint(ls[gid*LSP     + d0 + kl + tig]);
            a[1] = __float_as_uint(ls[(gid+8)*LSP + d0 + kl + tig]);
            a[2] = __float_as_uint(ls[gid*LSP     + d0 + kl + tig + 4]);
            a[3] = __float_as_uint(ls[(gid+8)*LSP + d0 + kl + tig + 4]);
#pragma unroll
            for (int nj = 0; nj < 4; ++nj) {
                uint32_t b0 = __float_as_uint(kv[(nj*8+gid)*CHP + kl + tig]);
                uint32_t b1 = __float_as_uint(kv[(nj*8+gid)*CHP + kl + tig + 4]);
                mma8(acc2[nj], a, b0, b1);
            }
        }
    }

    // partial stores
#pragma unroll
    for (int nj = 0; nj < 4; ++nj)
#pragma unroll
        for (int r = 0; r < 4; ++r) {
            int q = gid + ((r >> 1) << 3);
            int c = nj*8 + tig*2 + (r & 1);
            os[(wid*16 + q)*33 + c] = acc2[nj][r];
        }
    __syncthreads();   // all mma done (kv free), os complete

    // reduce partials into oq (reuse qs: 16*33 = 528 <= 576)
    float* oq = qs;
    for (int u = tid; u < 512; u += 256) {
        int q = u >> 5, c = u & 31;
        float s = 0.f;
#pragma unroll
        for (int w = 0; w < 8; ++w) s += os[(w*16 + q)*33 + c];
        oq[q*33 + c] = s;
    }
    // load gate weights/biases into kv area
    float* wsm = kv;             // 4*1024
    float* bsm = kv + 4096;      // 4*32
    for (int u = tid; u < 1024; u += 256) {
        int e = u >> 8, off = (u & 255)*4;
        const float* Wa = (e==0)?Wa_i:(e==1)?Wa_f:(e==2)?Wa_g:Wa_o;
        *reinterpret_cast<float4*>(wsm + e*1024 + off) =
            *reinterpret_cast<const float4*>(Wa + (size_t)g*1024 + off);
    }
    if (tid < 128) {
        int e = tid >> 5, c = tid & 31;
        const float* bb = (e==0)?b_i:(e==1)?b_f:(e==2)?b_g:b_o;
        bsm[tid] = bb[g*32 + c];
    }
    __syncthreads();

    // fused gates + cell update
    for (int u = tid; u < 512; u += 256) {
        int q = u & 15, c = u >> 4;
        float a0 = bsm[c], a1 = bsm[32+c], a2 = bsm[64+c], a3 = bsm[96+c];
#pragma unroll 8
        for (int cc = 0; cc < 32; ++cc) {
            float o = oq[q*33 + cc];
            a0 = fmaf(wsm[        c*32 + cc], o, a0);
            a1 = fmaf(wsm[1024 + c*32 + cc], o, a1);
            a2 = fmaf(wsm[2048 + c*32 + cc], o, a2);
            a3 = fmaf(wsm[3072 + c*32 + cc], o, a3);
        }
        size_t off = ((size_t)(n*CCH) + g*32 + c)*HWQ + q0 + q;
        float gi = sigm (a0 + g_gp[0][off]);
        float gf = sigm (a1 + g_gp[1][off]);
        float gg = ftanh(a2 + g_gp[2][off]);
        float go = sigm (a3 + g_gp[3][off]);
        float cn = gf * c_prev[off] + gi * gg;
        outp[off] = go * ftanh(cn);
    }
}

// ---------------- launch ----------------------------------------------------
extern "C" void kernel_launch(void* const* d_in, const int* in_sizes, int n_in,
                              void* d_out, int out_size)
{
    (void)in_sizes; (void)n_in; (void)out_size;
    const float* inp    = (const float*)d_in[0];
    const float* h_prev = (const float*)d_in[1];
    const float* c_prev = (const float*)d_in[2];
    const float* Wx     = (const float*)d_in[3];
    const float* Wxg    = (const float*)d_in[4];
    const float* tau    = (const float*)d_in[5];
    const float* Wq     = (const float*)d_in[6];
    const float* Wk     = (const float*)d_in[7];
    const float* Wv     = (const float*)d_in[8];
    const float* Wa_i   = (const float*)d_in[9];
    const float* Wxh_i  = (const float*)d_in[10];
    const float* b_i    = (const float*)d_in[11];
    const float* Wa_f   = (const float*)d_in[12];
    const float* Wxh_f  = (const float*)d_in[13];
    const float* b_f    = (const float*)d_in[14];
    const float* Wa_g   = (const float*)d_in[15];
    const float* Wxh_g  = (const float*)d_in[16];
    const float* b_g    = (const float*)d_in[17];
    const float* Wa_o   = (const float*)d_in[18];
    const float* Wxh_o  = (const float*)d_in[19];
    const float* b_o    = (const float*)d_in[20];
    float* out = (float*)d_out;

    const int SMEM_S = (ITSZ + 3*160*36) * 4;   // 225792
    const int SMEM_V = (ITSZ + 3*64*68)  * 4;   // 208896

    cudaFuncSetAttribute(attn_kernel,
                         cudaFuncAttributeMaxDynamicSharedMemorySize, ATTN_SMEM);
    cudaFuncSetAttribute(conv_mma_kernel<160,0,48,10,32>,
                         cudaFuncAttributeMaxDynamicSharedMemorySize, SMEM_S);
    cudaFuncSetAttribute(conv_mma_kernel<64,4,40,4,64>,
                         cudaFuncAttributeMaxDynamicSharedMemorySize, SMEM_V);

    zero_xh2_kernel<<<2048, 256>>>();
    wtrans_kernel<<<GG*224, 256>>>(Wq, Wxh_i, Wxh_f, Wxh_g, Wxh_o, Wk, Wv);
    proj_kernel<<<dim3(9, 32, 4), 256>>>(inp, h_prev, Wx, Wxg);
    conv_mma_kernel<160,0,48,10,32><<<dim3(9, 8, 4), 256, SMEM_S>>>();
    conv_mma_kernel<64,4,40,4,64><<<dim3(9, 8, 4), 256, SMEM_V>>>();
    attn_kernel<<<NN*GG*144, 256, ATTN_SMEM>>>(tau, Wa_i, Wa_f, Wa_g, Wa_o,
                                               b_i, b_f, b_g, b_o, c_prev, out);
}